// round 2
// baseline (speedup 1.0000x reference)
#include <cuda_runtime.h>
#include <cuda_bf16.h>
#include <math.h>

// PointTransformerLayer: B=1, N=1024, D=64, H_POS=64, H_ATTN=256
//
// Math restructuring:
//   pp[i]  = pos[i] @ pW1                       (precomputed, linear)
//   h_ij   = relu(pp_i - pp_j + pb1)            (elementwise)
//   rpe_ij = h_ij @ pW2 + pb2
//   g_ij   = q_i - k_j + rpe_ij                 (q,k,v precomputed)
//   u_ij   = relu(g_ij @ aW1 + ab1)
//   sim_ij = u_ij @ aW2            (+ab2 dropped: constant over j, softmax-invariant)
//   attn   = online softmax over j, per channel d
//   out[i,d] = sum_j attn_ijd * (v[j,d] + rpe_ijd)

#define NN 1024
#define DD 64

__device__ float g_q[NN * DD];
__device__ float g_k[NN * DD];
__device__ float g_v[NN * DD];
__device__ float g_pp[NN * DD];

// ---------------------------------------------------------------------------
// Precompute: q = x@Wq, k = x@Wk, v = x@Wv, pp = pos@pW1
// ---------------------------------------------------------------------------
__global__ void pt_precompute(const float* __restrict__ x,
                              const float* __restrict__ pos,
                              const float* __restrict__ Wq,
                              const float* __restrict__ Wk,
                              const float* __restrict__ Wv,
                              const float* __restrict__ pW1)
{
    const int i = blockIdx.x;
    const int d = threadIdx.x;  // 64 threads
    __shared__ float xr[DD];
    xr[d] = x[i * DD + d];
    __syncthreads();
    float aq = 0.f, ak = 0.f, av = 0.f;
    #pragma unroll 8
    for (int m = 0; m < DD; ++m) {
        float xv = xr[m];
        aq = fmaf(xv, Wq[m * DD + d], aq);
        ak = fmaf(xv, Wk[m * DD + d], ak);
        av = fmaf(xv, Wv[m * DD + d], av);
    }
    g_q[i * DD + d] = aq;
    g_k[i * DD + d] = ak;
    g_v[i * DD + d] = av;
    g_pp[i * DD + d] = pos[i * 2 + 0] * pW1[d] + pos[i * 2 + 1] * pW1[DD + d];
}

// ---------------------------------------------------------------------------
// Main kernel: one CTA per query i, 256 threads, j tiled by 64.
// Shared memory layout (float offsets):
// ---------------------------------------------------------------------------
#define OFF_AW1T 0                        // aW1 transposed: [c=256][m=64] stride 68 (16B-aligned rows)
#define OFF_AW2  (OFF_AW1T + 256 * 68)   // aW2 [c=256][d=64]
#define OFF_PW2  (OFF_AW2 + 256 * 64)    // pW2 [m=64][d=64]
#define OFF_R    (OFF_PW2 + 64 * 64)     // rpe tile [j=64][d=64] stride 65 (bank-conflict-free cols)
#define OFF_SIM  (OFF_R + 64 * 65)       // sim tile [j=64][d=64] stride 65
#define OFF_RED  (OFF_SIM + 64 * 65)     // 4x64 reduction scratch
#define OFF_RED2 (OFF_RED + 256)         // 4x64 reduction scratch
#define OFF_PPI  (OFF_RED2 + 256)        // pp[i] (64)
#define OFF_QI   (OFF_PPI + 64)          // q[i]  (64)
#define OFF_PB1  (OFF_QI + 64)
#define OFF_PB2  (OFF_PB1 + 64)
#define OFF_AB1  (OFF_PB2 + 64)          // 256
#define SMEM_FLOATS (OFF_AB1 + 256)      // 47232 floats = 188928 bytes

__global__ __launch_bounds__(256, 1) void pt_main(
    const float* __restrict__ pW2g, const float* __restrict__ pb1g,
    const float* __restrict__ pb2g, const float* __restrict__ aW1g,
    const float* __restrict__ ab1g, const float* __restrict__ aW2g,
    float* __restrict__ out)
{
    extern __shared__ float sm[];
    const int tid = threadIdx.x;
    const int i = blockIdx.x;

    // ---- cooperative weight/bias loads (all L2-resident, ~150KB) ----
    for (int idx = tid; idx < 64 * 256; idx += 256) {
        int m = idx >> 8, c = idx & 255;               // aW1 is [m][c]
        sm[OFF_AW1T + c * 68 + m] = aW1g[idx];         // store transposed [c][m]
    }
    for (int idx = tid; idx < 256 * 64; idx += 256) sm[OFF_AW2 + idx] = aW2g[idx];
    for (int idx = tid; idx < 64 * 64; idx += 256)  sm[OFF_PW2 + idx] = pW2g[idx];
    if (tid < 64) {
        sm[OFF_PPI + tid] = g_pp[i * 64 + tid];
        sm[OFF_QI + tid]  = g_q[i * 64 + tid];
        sm[OFF_PB1 + tid] = pb1g[tid];
        sm[OFF_PB2 + tid] = pb2g[tid];
    }
    sm[OFF_AB1 + tid] = ab1g[tid];
    __syncthreads();

    const int j  = tid & 63;   // j-lane within tile (also channel d in softmax phase)
    const int cg = tid >> 6;   // group 0..3 (c-range in MLP phase, j-range in softmax phase)

    float m_run = -1e30f, s_run = 0.f, a_run = 0.f;  // online-softmax state (channel j)

    for (int jt = 0; jt < 16; ++jt) {
        const int j0 = jt << 6;

        // ---- Phase B: h on the fly, rpe partial. Thread computes R[j][cg*16 .. +15]
        {
            float r[16];
            #pragma unroll
            for (int t = 0; t < 16; ++t) r[t] = sm[OFF_PB2 + cg * 16 + t];
            const float4* pp4 = reinterpret_cast<const float4*>(g_pp + (j0 + j) * 64);
            #pragma unroll 4
            for (int m4 = 0; m4 < 16; ++m4) {
                float4 p = pp4[m4];
                float h0 = fmaxf(sm[OFF_PPI + 4 * m4 + 0] - p.x + sm[OFF_PB1 + 4 * m4 + 0], 0.f);
                float h1 = fmaxf(sm[OFF_PPI + 4 * m4 + 1] - p.y + sm[OFF_PB1 + 4 * m4 + 1], 0.f);
                float h2 = fmaxf(sm[OFF_PPI + 4 * m4 + 2] - p.z + sm[OFF_PB1 + 4 * m4 + 2], 0.f);
                float h3 = fmaxf(sm[OFF_PPI + 4 * m4 + 3] - p.w + sm[OFF_PB1 + 4 * m4 + 3], 0.f);
                const float4* w0 = reinterpret_cast<const float4*>(sm + OFF_PW2 + (4 * m4 + 0) * 64 + cg * 16);
                const float4* w1 = reinterpret_cast<const float4*>(sm + OFF_PW2 + (4 * m4 + 1) * 64 + cg * 16);
                const float4* w2 = reinterpret_cast<const float4*>(sm + OFF_PW2 + (4 * m4 + 2) * 64 + cg * 16);
                const float4* w3 = reinterpret_cast<const float4*>(sm + OFF_PW2 + (4 * m4 + 3) * 64 + cg * 16);
                #pragma unroll
                for (int q4 = 0; q4 < 4; ++q4) {
                    float4 a = w0[q4], b = w1[q4], c2 = w2[q4], d2 = w3[q4];
                    r[4 * q4 + 0] = fmaf(h3, d2.x, fmaf(h2, c2.x, fmaf(h1, b.x, fmaf(h0, a.x, r[4 * q4 + 0]))));
                    r[4 * q4 + 1] = fmaf(h3, d2.y, fmaf(h2, c2.y, fmaf(h1, b.y, fmaf(h0, a.y, r[4 * q4 + 1]))));
                    r[4 * q4 + 2] = fmaf(h3, d2.z, fmaf(h2, c2.z, fmaf(h1, b.z, fmaf(h0, a.z, r[4 * q4 + 2]))));
                    r[4 * q4 + 3] = fmaf(h3, d2.w, fmaf(h2, c2.w, fmaf(h1, b.w, fmaf(h0, a.w, r[4 * q4 + 3]))));
                }
            }
            #pragma unroll
            for (int t = 0; t < 16; ++t) sm[OFF_R + j * 65 + cg * 16 + t] = r[t];
        }
        __syncthreads();

        // ---- Phase C: g = q_i - k_j + rpe (register-resident, same for all cg of a j)
        float greg[64];
        {
            const float4* k4 = reinterpret_cast<const float4*>(g_k + (j0 + j) * 64);
            #pragma unroll
            for (int m4 = 0; m4 < 16; ++m4) {
                float4 kv = k4[m4];
                greg[4 * m4 + 0] = sm[OFF_QI + 4 * m4 + 0] - kv.x + sm[OFF_R + j * 65 + 4 * m4 + 0];
                greg[4 * m4 + 1] = sm[OFF_QI + 4 * m4 + 1] - kv.y + sm[OFF_R + j * 65 + 4 * m4 + 1];
                greg[4 * m4 + 2] = sm[OFF_QI + 4 * m4 + 2] - kv.z + sm[OFF_R + j * 65 + 4 * m4 + 2];
                greg[4 * m4 + 3] = sm[OFF_QI + 4 * m4 + 3] - kv.w + sm[OFF_R + j * 65 + 4 * m4 + 3];
            }
        }

        // ---- Phase D: u = relu(g@aW1+ab1) over this cg's 64 c's; sim partial = u@aW2
        float simreg[64];
        #pragma unroll
        for (int t = 0; t < 64; ++t) simreg[t] = 0.f;
        #pragma unroll 2
        for (int cc = 0; cc < 64; ++cc) {
            const int c = (cg << 6) + cc;
            const float4* w4 = reinterpret_cast<const float4*>(sm + OFF_AW1T + c * 68);
            float u0 = 0.f, u1 = 0.f, u2 = 0.f, u3 = 0.f;
            #pragma unroll
            for (int m4 = 0; m4 < 16; ++m4) {
                float4 w = w4[m4];
                u0 = fmaf(greg[4 * m4 + 0], w.x, u0);
                u1 = fmaf(greg[4 * m4 + 1], w.y, u1);
                u2 = fmaf(greg[4 * m4 + 2], w.z, u2);
                u3 = fmaf(greg[4 * m4 + 3], w.w, u3);
            }
            float u = fmaxf((u0 + u1) + (u2 + u3) + sm[OFF_AB1 + c], 0.f);
            const float4* a4 = reinterpret_cast<const float4*>(sm + OFF_AW2 + c * 64);
            #pragma unroll
            for (int d4 = 0; d4 < 16; ++d4) {
                float4 a = a4[d4];
                simreg[4 * d4 + 0] = fmaf(u, a.x, simreg[4 * d4 + 0]);
                simreg[4 * d4 + 1] = fmaf(u, a.y, simreg[4 * d4 + 1]);
                simreg[4 * d4 + 2] = fmaf(u, a.z, simreg[4 * d4 + 2]);
                simreg[4 * d4 + 3] = fmaf(u, a.w, simreg[4 * d4 + 3]);
            }
        }

        // ---- sim reduction across the 4 cg groups (sequential, 4 steps)
        if (cg == 0) {
            #pragma unroll
            for (int t = 0; t < 64; ++t) sm[OFF_SIM + j * 65 + t] = simreg[t];
        }
        __syncthreads();
        if (cg == 1) {
            #pragma unroll
            for (int t = 0; t < 64; ++t) sm[OFF_SIM + j * 65 + t] += simreg[t];
        }
        __syncthreads();
        if (cg == 2) {
            #pragma unroll
            for (int t = 0; t < 64; ++t) sm[OFF_SIM + j * 65 + t] += simreg[t];
        }
        __syncthreads();
        if (cg == 3) {
            #pragma unroll
            for (int t = 0; t < 64; ++t) sm[OFF_SIM + j * 65 + t] += simreg[t];
        }
        __syncthreads();

        // ---- Phase E: online softmax update. Roles: channel d = j, j-range = cg.
        {
            float lmax = -1e30f;
            #pragma unroll
            for (int t = 0; t < 16; ++t)
                lmax = fmaxf(lmax, sm[OFF_SIM + (cg * 16 + t) * 65 + j]);
            sm[OFF_RED + cg * 64 + j] = lmax;
            __syncthreads();
            float tmax = fmaxf(fmaxf(sm[OFF_RED + j], sm[OFF_RED + 64 + j]),
                               fmaxf(sm[OFF_RED + 128 + j], sm[OFF_RED + 192 + j]));
            float m_new = fmaxf(m_run, tmax);
            float corr = __expf(m_run - m_new);
            float ps = 0.f, pa = 0.f;
            #pragma unroll
            for (int t = 0; t < 16; ++t) {
                int jj = cg * 16 + t;
                float e = __expf(sm[OFF_SIM + jj * 65 + j] - m_new);
                ps += e;
                pa = fmaf(e, g_v[(j0 + jj) * 64 + j] + sm[OFF_R + jj * 65 + j], pa);
            }
            __syncthreads();  // red buffers reused
            sm[OFF_RED + cg * 64 + j] = ps;
            sm[OFF_RED2 + cg * 64 + j] = pa;
            __syncthreads();
            float S = sm[OFF_RED + j] + sm[OFF_RED + 64 + j] +
                      sm[OFF_RED + 128 + j] + sm[OFF_RED + 192 + j];
            float A = sm[OFF_RED2 + j] + sm[OFF_RED2 + 64 + j] +
                      sm[OFF_RED2 + 128 + j] + sm[OFF_RED2 + 192 + j];
            s_run = s_run * corr + S;
            a_run = a_run * corr + A;
            m_run = m_new;
        }
    }

    if (cg == 0) out[i * 64 + j] = a_run / s_run;
}

// ---------------------------------------------------------------------------
extern "C" void kernel_launch(void* const* d_in, const int* in_sizes, int n_in,
                              void* d_out, int out_size)
{
    const float* x   = (const float*)d_in[0];
    const float* pos = (const float*)d_in[1];
    const float* Wq  = (const float*)d_in[2];
    const float* Wk  = (const float*)d_in[3];
    const float* Wv  = (const float*)d_in[4];
    const float* pW1 = (const float*)d_in[5];
    const float* pb1 = (const float*)d_in[6];
    const float* pW2 = (const float*)d_in[7];
    const float* pb2 = (const float*)d_in[8];
    const float* aW1 = (const float*)d_in[9];
    const float* ab1 = (const float*)d_in[10];
    const float* aW2 = (const float*)d_in[11];
    // d_in[12] = ab2: constant over j, cancels in the per-channel softmax -> unused.
    float* out = (float*)d_out;

    (void)in_sizes; (void)n_in; (void)out_size;

    cudaFuncSetAttribute(pt_main, cudaFuncAttributeMaxDynamicSharedMemorySize,
                         SMEM_FLOATS * (int)sizeof(float));

    pt_precompute<<<NN, DD>>>(x, pos, Wq, Wk, Wv, pW1);
    pt_main<<<NN, 256, SMEM_FLOATS * sizeof(float)>>>(pW2, pb1, pb2, aW1, ab1, aW2, out);
}

// round 4
// speedup vs baseline: 3.9254x; 3.9254x over previous
#include <cuda_runtime.h>
#include <cuda_bf16.h>
#include <stdint.h>
#include <math.h>

// PointTransformerLayer via warp-level bf16 HMMA (mma.sync m16n8k16), sm_103-safe PTX.
// B=1, N=1024, D=64, H_POS=64, H_ATTN=256.
//   pp = pos@pW1;  h = relu(pp_i - pp_j + pb1);  rpe = h@pW2;  rp2 = rpe + pb2
//   g = q_i - k_j + rp2;  u = relu(g@aW1 + ab1);  sim = u@aW2   (ab2 cancels in softmax)
//   out[i,d] = softmax_j(sim[:,d]) . (v[j,d] + rp2[j,d])
// GEMMs: bf16 hi/lo 3-term (Ah*Bh + Ah*Bl + Al*Bh), fp32 accum.
// Activations stay in registers: accum-fragment of one GEMM == A-fragment of the next.

#define NN 1024
#define DD 64
#define HH 256

__device__ __align__(16) float g_q[NN*DD];
__device__ __align__(16) float g_k[NN*DD];
__device__ __align__(16) float g_v[NN*DD];
__device__ __align__(16) float g_pp[NN*DD];
__device__ __align__(16) __nv_bfloat16 W1Hg[DD*DD],  W1Lg[DD*DD];   // pW2^T [d][m]
__device__ __align__(16) __nv_bfloat16 W2Hg[HH*DD],  W2Lg[HH*DD];   // aW1^T [c][m]
__device__ __align__(16) __nv_bfloat16 W3Hg[DD*HH],  W3Lg[DD*HH];   // aW2^T [d][c]

// ---------------- smem layout (bytes) ----------------
// padded strides (elems): W1/W2: 72, W3: 264, rpe/sim: 65
#define O_W1H 0
#define O_W1L 9216
#define O_W2H 18432
#define O_W2L 55296
#define O_W3H 92160
#define O_W3L 125952
#define O_RPE 159744
#define O_SIM 193024
#define O_AB1 226304
#define O_RED 227328
#define O_RED2 228352
#define O_QIS 229376
#define O_PB2S 229632
#define O_PBPS 229888
#define SMEM_TOTAL 230400

__device__ __forceinline__ uint32_t smem_u32(const void* p) {
    uint32_t a;
    asm("{ .reg .u64 t; cvta.to.shared.u64 t, %1; cvt.u32.u64 %0, t; }" : "=r"(a) : "l"(p));
    return a;
}
__device__ __forceinline__ void ldsm_x2(uint32_t& r0, uint32_t& r1, uint32_t addr) {
    asm volatile("ldmatrix.sync.aligned.m8n8.x2.shared.b16 {%0,%1}, [%2];"
                 : "=r"(r0), "=r"(r1) : "r"(addr));
}
__device__ __forceinline__ void mma16816(float* c, const uint32_t* a, uint32_t b0, uint32_t b1) {
    asm volatile("mma.sync.aligned.m16n8k16.row.col.f32.bf16.bf16.f32 "
                 "{%0,%1,%2,%3}, {%4,%5,%6,%7}, {%8,%9}, {%0,%1,%2,%3};"
                 : "+f"(c[0]), "+f"(c[1]), "+f"(c[2]), "+f"(c[3])
                 : "r"(a[0]), "r"(a[1]), "r"(a[2]), "r"(a[3]), "r"(b0), "r"(b1));
}
// 3-term: acc += Ah*Bh + Ah*Bl + Al*Bh
__device__ __forceinline__ void mma3(float* c, const uint32_t* aH, const uint32_t* aL,
                                     uint32_t bhA, uint32_t blA) {
    uint32_t h0, h1, l0, l1;
    ldsm_x2(h0, h1, bhA);
    ldsm_x2(l0, l1, blA);
    mma16816(c, aH, h0, h1);
    mma16816(c, aH, l0, l1);
    mma16816(c, aL, h0, h1);
}
__device__ __forceinline__ void split2(float a, float b, uint32_t& hi, uint32_t& lo) {
    __nv_bfloat16 ah = __float2bfloat16(a), bh = __float2bfloat16(b);
    float ar = a - __bfloat162float(ah), br = b - __bfloat162float(bh);
    __nv_bfloat16 al = __float2bfloat16(ar), bl = __float2bfloat16(br);
    hi = (uint32_t)__bfloat16_as_ushort(ah) | ((uint32_t)__bfloat16_as_ushort(bh) << 16);
    lo = (uint32_t)__bfloat16_as_ushort(al) | ((uint32_t)__bfloat16_as_ushort(bl) << 16);
}

// ---------------- precompute ----------------
__global__ void pt_precompute(const float* __restrict__ x, const float* __restrict__ pos,
                              const float* __restrict__ Wq, const float* __restrict__ Wk,
                              const float* __restrict__ Wv, const float* __restrict__ pW1)
{
    const int i = blockIdx.x, d = threadIdx.x;
    __shared__ float xr[DD];
    xr[d] = x[i * DD + d];
    __syncthreads();
    float aq = 0.f, ak = 0.f, av = 0.f;
    #pragma unroll 8
    for (int m = 0; m < DD; ++m) {
        float xv = xr[m];
        aq = fmaf(xv, Wq[m * DD + d], aq);
        ak = fmaf(xv, Wk[m * DD + d], ak);
        av = fmaf(xv, Wv[m * DD + d], av);
    }
    g_q[i * DD + d] = aq; g_k[i * DD + d] = ak; g_v[i * DD + d] = av;
    g_pp[i * DD + d] = pos[i * 2 + 0] * pW1[d] + pos[i * 2 + 1] * pW1[DD + d];
}

__global__ void wconvert(const float* __restrict__ pW2, const float* __restrict__ aW1,
                         const float* __restrict__ aW2)
{
    int idx = blockIdx.x * blockDim.x + threadIdx.x;
    const int t1 = DD * DD, t2 = t1 + HH * DD, t3 = t2 + DD * HH;
    if (idx < t1) {
        int d = idx >> 6, m = idx & 63;
        float w = pW2[m * DD + d];
        __nv_bfloat16 h = __float2bfloat16(w);
        W1Hg[idx] = h; W1Lg[idx] = __float2bfloat16(w - __bfloat162float(h));
    } else if (idx < t2) {
        int k = idx - t1; int c = k >> 6, m = k & 63;
        float w = aW1[m * HH + c];
        __nv_bfloat16 h = __float2bfloat16(w);
        W2Hg[k] = h; W2Lg[k] = __float2bfloat16(w - __bfloat162float(h));
    } else if (idx < t3) {
        int k = idx - t2; int d = k >> 8, c = k & 255;
        float w = aW2[c * DD + d];
        __nv_bfloat16 h = __float2bfloat16(w);
        W3Hg[k] = h; W3Lg[k] = __float2bfloat16(w - __bfloat162float(h));
    }
}

// ---------------- main: one CTA per query i, 256 threads, j tiled by 128 ----------------
__global__ __launch_bounds__(256, 1) void pt_main(
    const float* __restrict__ pb1g, const float* __restrict__ pb2g,
    const float* __restrict__ ab1g, float* __restrict__ out)
{
    extern __shared__ __align__(16) char smem[];
    const uint32_t sb = smem_u32(smem);
    const int tid = threadIdx.x;
    const int i = blockIdx.x;

    // ---- stage weights (padded rows) ----
    {
        const uint4* s;
        s = (const uint4*)W1Hg;
        for (int u = tid; u < 512; u += 256)
            *(uint4*)(smem + O_W1H + (u >> 3) * 144 + (u & 7) * 16) = s[u];
        s = (const uint4*)W1Lg;
        for (int u = tid; u < 512; u += 256)
            *(uint4*)(smem + O_W1L + (u >> 3) * 144 + (u & 7) * 16) = s[u];
        s = (const uint4*)W2Hg;
        for (int u = tid; u < 2048; u += 256)
            *(uint4*)(smem + O_W2H + (u >> 3) * 144 + (u & 7) * 16) = s[u];
        s = (const uint4*)W2Lg;
        for (int u = tid; u < 2048; u += 256)
            *(uint4*)(smem + O_W2L + (u >> 3) * 144 + (u & 7) * 16) = s[u];
        s = (const uint4*)W3Hg;
        for (int u = tid; u < 2048; u += 256)
            *(uint4*)(smem + O_W3H + (u >> 5) * 528 + (u & 31) * 16) = s[u];
        s = (const uint4*)W3Lg;
        for (int u = tid; u < 2048; u += 256)
            *(uint4*)(smem + O_W3L + (u >> 5) * 528 + (u & 31) * 16) = s[u];
    }
    float* ab1s  = (float*)(smem + O_AB1);
    float* red   = (float*)(smem + O_RED);
    float* red2  = (float*)(smem + O_RED2);
    float* qis   = (float*)(smem + O_QIS);
    float* pb2s  = (float*)(smem + O_PB2S);
    float* pbps  = (float*)(smem + O_PBPS);
    float* rpeb  = (float*)(smem + O_RPE);
    float* simb  = (float*)(smem + O_SIM);
    if (tid < 64) {
        qis[tid]  = g_q[i * 64 + tid];
        pb2s[tid] = pb2g[tid];
        pbps[tid] = g_pp[i * 64 + tid] + pb1g[tid];   // ppi + pb1
    }
    ab1s[tid] = ab1g[tid];
    __syncthreads();

    const int lane = tid & 31, warp = tid >> 5;
    const int wb = warp * 16;
    const int rquad = lane >> 2;     // 0..7
    const int tpair = lane & 3;      // 0..3
    const int l16 = lane & 15;
    const int r8 = l16 & 7, hf = l16 >> 3;
    const int pcol = 2 * tpair;

    // softmax roles
    const int d = tid & 63, qq = tid >> 6;
    float m_run = -1e30f, s_run = 0.f, a_run = 0.f;

    for (int jt = 0; jt < 8; ++jt) {
        const int j0 = jt * 128;
        const int jr0 = j0 + wb + rquad;        // global j of row r, (+8 for second)

        // ===== G1: rpe = h @ W1 (K=64, N=64) =====
        float rp[8][4];
        {
            uint32_t hH[4][4], hL[4][4];
            #pragma unroll
            for (int kt = 0; kt < 4; ++kt) {
                #pragma unroll
                for (int s2 = 0; s2 < 2; ++s2) {
                    int kk = kt * 16 + s2 * 8 + pcol;
                    float2 bb = *(const float2*)(pbps + kk);
                    float2 p0 = *(const float2*)(g_pp + jr0 * 64 + kk);
                    float2 p1 = *(const float2*)(g_pp + (jr0 + 8) * 64 + kk);
                    split2(fmaxf(bb.x - p0.x, 0.f), fmaxf(bb.y - p0.y, 0.f),
                           hH[kt][s2 * 2 + 0], hL[kt][s2 * 2 + 0]);
                    split2(fmaxf(bb.x - p1.x, 0.f), fmaxf(bb.y - p1.y, 0.f),
                           hH[kt][s2 * 2 + 1], hL[kt][s2 * 2 + 1]);
                }
            }
            #pragma unroll
            for (int nt = 0; nt < 8; ++nt) {
                #pragma unroll
                for (int r2 = 0; r2 < 4; ++r2) rp[nt][r2] = 0.f;
                #pragma unroll
                for (int kt = 0; kt < 4; ++kt) {
                    uint32_t off = (uint32_t)(((nt * 8 + r8) * 72 + kt * 16 + hf * 8) * 2);
                    mma3(rp[nt], hH[kt], hL[kt], sb + O_W1H + off, sb + O_W1L + off);
                }
            }
        }

        // ===== rp2 = rpe + pb2 -> smem; g-frags (A of G2) =====
        uint32_t gH[4][4], gL[4][4];
        #pragma unroll
        for (int nt = 0; nt < 8; ++nt) {
            int col = 8 * nt + pcol;
            float2 pb2v = *(const float2*)(pb2s + col);
            float2 qv   = *(const float2*)(qis + col);
            float2 k0   = *(const float2*)(g_k + jr0 * 64 + col);
            float2 k1   = *(const float2*)(g_k + (jr0 + 8) * 64 + col);
            float r00 = rp[nt][0] + pb2v.x, r01 = rp[nt][1] + pb2v.y;
            float r10 = rp[nt][2] + pb2v.x, r11 = rp[nt][3] + pb2v.y;
            float* rw0 = rpeb + (wb + rquad) * 65 + col;
            float* rw1 = rpeb + (wb + rquad + 8) * 65 + col;
            rw0[0] = r00; rw0[1] = r01; rw1[0] = r10; rw1[1] = r11;
            int ktg = nt >> 1, rb = (nt & 1) * 2;
            split2(qv.x - k0.x + r00, qv.y - k0.y + r01, gH[ktg][rb + 0], gL[ktg][rb + 0]);
            split2(qv.x - k1.x + r10, qv.y - k1.y + r11, gH[ktg][rb + 1], gL[ktg][rb + 1]);
        }

        // ===== G2 (z = g@W2 + ab1, relu) fused with G3 (sim += u@W3), H in 4 chunks =====
        float sa[8][4];
        #pragma unroll
        for (int nt = 0; nt < 8; ++nt)
            #pragma unroll
            for (int r2 = 0; r2 < 4; ++r2) sa[nt][r2] = 0.f;

        #pragma unroll
        for (int ci = 0; ci < 4; ++ci) {
            uint32_t uH[4][4], uL[4][4];
            #pragma unroll
            for (int nt = 0; nt < 8; ++nt) {
                float za[4] = {0.f, 0.f, 0.f, 0.f};
                #pragma unroll
                for (int kt = 0; kt < 4; ++kt) {
                    uint32_t off = (uint32_t)((((ci * 64 + nt * 8) + r8) * 72 + kt * 16 + hf * 8) * 2);
                    mma3(za, gH[kt], gL[kt], sb + O_W2H + off, sb + O_W2L + off);
                }
                int c = ci * 64 + 8 * nt + pcol;
                float2 ab = *(const float2*)(ab1s + c);
                int ktu = nt >> 1, rb = (nt & 1) * 2;
                split2(fmaxf(za[0] + ab.x, 0.f), fmaxf(za[1] + ab.y, 0.f),
                       uH[ktu][rb + 0], uL[ktu][rb + 0]);
                split2(fmaxf(za[2] + ab.x, 0.f), fmaxf(za[3] + ab.y, 0.f),
                       uH[ktu][rb + 1], uL[ktu][rb + 1]);
            }
            #pragma unroll
            for (int nt = 0; nt < 8; ++nt) {
                #pragma unroll
                for (int kt = 0; kt < 4; ++kt) {
                    uint32_t off = (uint32_t)(((nt * 8 + r8) * 264 + ci * 64 + kt * 16 + hf * 8) * 2);
                    mma3(sa[nt], uH[kt], uL[kt], sb + O_W3H + off, sb + O_W3L + off);
                }
            }
        }

        // ===== sim -> smem =====
        #pragma unroll
        for (int nt = 0; nt < 8; ++nt) {
            int col = 8 * nt + pcol;
            float* sw0 = simb + (wb + rquad) * 65 + col;
            float* sw1 = simb + (wb + rquad + 8) * 65 + col;
            sw0[0] = sa[nt][0]; sw0[1] = sa[nt][1];
            sw1[0] = sa[nt][2]; sw1[1] = sa[nt][3];
        }
        __syncthreads();

        // ===== online softmax over j (thread = (quarter qq, channel d)) =====
        {
            float lmax = -1e30f;
            #pragma unroll 8
            for (int r = 0; r < 32; ++r)
                lmax = fmaxf(lmax, simb[(qq * 32 + r) * 65 + d]);
            red[qq * 64 + d] = lmax;
            __syncthreads();
            float tmax = fmaxf(fmaxf(red[d], red[64 + d]), fmaxf(red[128 + d], red[192 + d]));
            float m_new = fmaxf(m_run, tmax);
            float corr = __expf(m_run - m_new);
            float ps = 0.f, pa = 0.f;
            #pragma unroll 4
            for (int r = 0; r < 32; ++r) {
                int rr = qq * 32 + r;
                float e = __expf(simb[rr * 65 + d] - m_new);
                ps += e;
                pa = fmaf(e, g_v[(j0 + rr) * 64 + d] + rpeb[rr * 65 + d], pa);
            }
            __syncthreads();
            red[qq * 64 + d] = ps;
            red2[qq * 64 + d] = pa;
            __syncthreads();
            float S = red[d] + red[64 + d] + red[128 + d] + red[192 + d];
            float A = red2[d] + red2[64 + d] + red2[128 + d] + red2[192 + d];
            s_run = s_run * corr + S;
            a_run = a_run * corr + A;
            m_run = m_new;
            __syncthreads();   // before next tile overwrites rpe/sim
        }
    }

    if (qq == 0) out[i * 64 + d] = a_run / s_run;
}

// ---------------------------------------------------------------------------
extern "C" void kernel_launch(void* const* d_in, const int* in_sizes, int n_in,
                              void* d_out, int out_size)
{
    const float* x   = (const float*)d_in[0];
    const float* pos = (const float*)d_in[1];
    const float* Wq  = (const float*)d_in[2];
    const float* Wk  = (const float*)d_in[3];
    const float* Wv  = (const float*)d_in[4];
    const float* pW1 = (const float*)d_in[5];
    const float* pb1 = (const float*)d_in[6];
    const float* pW2 = (const float*)d_in[7];
    const float* pb2 = (const float*)d_in[8];
    const float* aW1 = (const float*)d_in[9];
    const float* ab1 = (const float*)d_in[10];
    const float* aW2 = (const float*)d_in[11];
    // d_in[12] = ab2: constant over j, cancels in per-channel softmax.
    float* out = (float*)d_out;
    (void)in_sizes; (void)n_in; (void)out_size;

    cudaFuncSetAttribute(pt_main, cudaFuncAttributeMaxDynamicSharedMemorySize, SMEM_TOTAL);

    pt_precompute<<<NN, DD>>>(x, pos, Wq, Wk, Wv, pW1);
    wconvert<<<(DD*DD + HH*DD + DD*HH + 255) / 256, 256>>>(pW2, aW1, aW2);
    pt_main<<<NN, 256, SMEM_TOTAL>>>(pb1, pb2, ab1, out);
}

// round 5
// speedup vs baseline: 4.3240x; 1.1015x over previous
#include <cuda_runtime.h>
#include <cuda_bf16.h>
#include <stdint.h>
#include <math.h>

// PointTransformerLayer via bf16 HMMA (mma.sync m16n8k16), sm_103-safe PTX.
// B=1, N=1024, D=64, H_POS=64, H_ATTN=256.
// Algebra: pp = pos@pW1;  h = relu(pp_i - pp_j + pb1);  rpe = h@pW2
//   z = g@aW1 + ab1  with g = q_i - k_j + rpe + pb2  distributes to
//   z = h@M + qa_i - ka_j + cz,  M = pW2@aW1, qa = q@aW1, ka = k@aW1, cz = pb2@aW1 + ab1
//   u = relu(z);  sim = u@aW2  (ab2 cancels in per-channel softmax)
//   out[i,d] = softmax_j(sim[:,d]) . (v[j,d] + rpe[j,d] + pb2[d])
// 3-term bf16 hi/lo split GEMMs (Ah*Bh + Ah*Bl + Al*Bh), fp32 accumulate.
// Softmax fully register-resident: butterfly shuffles per warp stripe, one final merge.

#define NN 1024
#define DD 64
#define HH 256

__device__ __align__(16) float g_q[NN*DD];
__device__ __align__(16) float g_k[NN*DD];
__device__ __align__(16) float g_v[NN*DD];
__device__ __align__(16) float g_pp[NN*DD];
__device__ __align__(16) float g_qa[NN*HH];
__device__ __align__(16) float g_ka[NN*HH];
__device__ __align__(16) float g_Mt[DD*HH];      // M[m][c] = sum_d pW2[m,d] aW1[d,c]
__device__ __align__(16) float g_cz[HH];
__device__ __align__(16) __nv_bfloat16 W1Hg[DD*DD],  W1Lg[DD*DD];   // pW2^T [d][m]
__device__ __align__(16) __nv_bfloat16 W2Hg[HH*DD],  W2Lg[HH*DD];   // M^T   [c][m]
__device__ __align__(16) __nv_bfloat16 W3Hg[DD*HH],  W3Lg[DD*HH];   // aW2^T [d][c]

// ---------------- smem layout (bytes) ----------------
// HI block: W1 @0 (64x144B), W2 @9216 (256x144B), W3 @46080 (64x528B) -> end 79872
// LO block: same layout at +LODELTA.
#define LODELTA 81920
#define O_W1 0
#define O_W2 9216
#define O_W3 46080
#define O_PBPS 161792
#define O_PB2S 162048
#define O_QACZ 162304
#define O_MRG_M 163328
#define O_MRG_S 165376
#define O_MRG_A 167424
#define SMEM_TOTAL 169472

__device__ __forceinline__ uint32_t smem_u32(const void* p) {
    uint32_t a;
    asm("{ .reg .u64 t; cvta.to.shared.u64 t, %1; cvt.u32.u64 %0, t; }" : "=r"(a) : "l"(p));
    return a;
}
__device__ __forceinline__ void mma16816(float* c, const uint32_t* a, uint32_t b0, uint32_t b1) {
    asm volatile("mma.sync.aligned.m16n8k16.row.col.f32.bf16.bf16.f32 "
                 "{%0,%1,%2,%3}, {%4,%5,%6,%7}, {%8,%9}, {%0,%1,%2,%3};"
                 : "+f"(c[0]), "+f"(c[1]), "+f"(c[2]), "+f"(c[3])
                 : "r"(a[0]), "r"(a[1]), "r"(a[2]), "r"(a[3]), "r"(b0), "r"(b1));
}
// One x4 ldmatrix fetches hi(b0,b1) + lo(b0,b1); 3-term MMA.
__device__ __forceinline__ void mma3(float* c, const uint32_t* aH, const uint32_t* aL, uint32_t addr) {
    uint32_t h0, h1, l0, l1;
    asm volatile("ldmatrix.sync.aligned.m8n8.x4.shared.b16 {%0,%1,%2,%3}, [%4];"
                 : "=r"(h0), "=r"(h1), "=r"(l0), "=r"(l1) : "r"(addr));
    mma16816(c, aH, h0, h1);
    mma16816(c, aH, l0, l1);
    mma16816(c, aL, h0, h1);
}
// fast hi/lo split: one bf16x2 cvt for hi, residuals, one cvt for lo.  (a -> low half)
__device__ __forceinline__ void split2(float a, float b, uint32_t& hi, uint32_t& lo) {
    __nv_bfloat162 hp = __floats2bfloat162_rn(a, b);
    uint32_t h = *reinterpret_cast<uint32_t*>(&hp);
    float af = __low2float(hp), bf = __high2float(hp);
    __nv_bfloat162 lp = __floats2bfloat162_rn(a - af, b - bf);
    hi = h;
    lo = *reinterpret_cast<uint32_t*>(&lp);
}

// ---------------- precompute: q,k,v,pp ----------------
__global__ void pt_precompute(const float* __restrict__ x, const float* __restrict__ pos,
                              const float* __restrict__ Wq, const float* __restrict__ Wk,
                              const float* __restrict__ Wv, const float* __restrict__ pW1)
{
    const int i = blockIdx.x * 4 + threadIdx.y;
    const int d = threadIdx.x;
    __shared__ float xr[4][DD];
    xr[threadIdx.y][d] = x[i * DD + d];
    __syncthreads();
    float aq = 0.f, ak = 0.f, av = 0.f;
    #pragma unroll 8
    for (int m = 0; m < DD; ++m) {
        float xv = xr[threadIdx.y][m];
        aq = fmaf(xv, Wq[m * DD + d], aq);
        ak = fmaf(xv, Wk[m * DD + d], ak);
        av = fmaf(xv, Wv[m * DD + d], av);
    }
    g_q[i * DD + d] = aq; g_k[i * DD + d] = ak; g_v[i * DD + d] = av;
    g_pp[i * DD + d] = pos[i * 2 + 0] * pW1[d] + pos[i * 2 + 1] * pW1[DD + d];
}

// ---------------- aux: qa, ka, M, cz ----------------
__global__ void pt_aux(const float* __restrict__ aW1, const float* __restrict__ pW2,
                       const float* __restrict__ pb2, const float* __restrict__ ab1)
{
    const int blk = blockIdx.x, c = threadIdx.x;
    __shared__ float sh[128];
    if (blk < NN) {
        if (c < 64) { sh[c] = g_q[blk * 64 + c]; sh[64 + c] = g_k[blk * 64 + c]; }
        __syncthreads();
        float accq = 0.f, acck = 0.f;
        #pragma unroll 8
        for (int dd = 0; dd < 64; ++dd) {
            float w = aW1[dd * HH + c];
            accq = fmaf(sh[dd], w, accq);
            acck = fmaf(sh[64 + dd], w, acck);
        }
        g_qa[blk * HH + c] = accq;
        g_ka[blk * HH + c] = acck;
    } else if (blk < NN + 64) {
        int m = blk - NN;
        if (c < 64) sh[c] = pW2[m * 64 + c];
        __syncthreads();
        float acc = 0.f;
        #pragma unroll 8
        for (int dd = 0; dd < 64; ++dd) acc = fmaf(sh[dd], aW1[dd * HH + c], acc);
        g_Mt[m * HH + c] = acc;
    } else {
        float acc = ab1[c];
        #pragma unroll 8
        for (int dd = 0; dd < 64; ++dd) acc = fmaf(pb2[dd], aW1[dd * HH + c], acc);
        g_cz[c] = acc;
    }
}

// ---------------- weight hi/lo split + transpose ----------------
__global__ void wconvert(const float* __restrict__ pW2, const float* __restrict__ aW2)
{
    int idx = blockIdx.x * blockDim.x + threadIdx.x;
    const int t1 = DD * DD, t2 = t1 + HH * DD, t3 = t2 + DD * HH;
    if (idx < t1) {
        int d = idx >> 6, m = idx & 63;
        float w = pW2[m * DD + d];
        __nv_bfloat16 h = __float2bfloat16(w);
        W1Hg[idx] = h; W1Lg[idx] = __float2bfloat16(w - __bfloat162float(h));
    } else if (idx < t2) {
        int k = idx - t1; int c = k >> 6, m = k & 63;
        float w = g_Mt[m * HH + c];
        __nv_bfloat16 h = __float2bfloat16(w);
        W2Hg[k] = h; W2Lg[k] = __float2bfloat16(w - __bfloat162float(h));
    } else if (idx < t3) {
        int k = idx - t2; int d = k >> 8, c = k & 255;
        float w = aW2[c * DD + d];
        __nv_bfloat16 h = __float2bfloat16(w);
        W3Hg[k] = h; W3Lg[k] = __float2bfloat16(w - __bfloat162float(h));
    }
}

// ---------------- main: one CTA per query i, 256 threads, j tiled by 128 ----------------
__global__ __launch_bounds__(256, 1) void pt_main(
    const float* __restrict__ pb1g, const float* __restrict__ pb2g,
    float* __restrict__ out)
{
    extern __shared__ __align__(16) char smem[];
    const uint32_t sb = smem_u32(smem);
    const int tid = threadIdx.x;
    const int i = blockIdx.x;

    // ---- stage weights: hi block + lo mirror at +LODELTA ----
    {
        const uint4* s;
        s = (const uint4*)W1Hg;
        for (int u = tid; u < 512; u += 256)
            *(uint4*)(smem + O_W1 + (u >> 3) * 144 + (u & 7) * 16) = s[u];
        s = (const uint4*)W1Lg;
        for (int u = tid; u < 512; u += 256)
            *(uint4*)(smem + O_W1 + LODELTA + (u >> 3) * 144 + (u & 7) * 16) = s[u];
        s = (const uint4*)W2Hg;
        for (int u = tid; u < 2048; u += 256)
            *(uint4*)(smem + O_W2 + (u >> 3) * 144 + (u & 7) * 16) = s[u];
        s = (const uint4*)W2Lg;
        for (int u = tid; u < 2048; u += 256)
            *(uint4*)(smem + O_W2 + LODELTA + (u >> 3) * 144 + (u & 7) * 16) = s[u];
        s = (const uint4*)W3Hg;
        for (int u = tid; u < 2048; u += 256)
            *(uint4*)(smem + O_W3 + (u >> 5) * 528 + (u & 31) * 16) = s[u];
        s = (const uint4*)W3Lg;
        for (int u = tid; u < 2048; u += 256)
            *(uint4*)(smem + O_W3 + LODELTA + (u >> 5) * 528 + (u & 31) * 16) = s[u];
    }
    float* pbps = (float*)(smem + O_PBPS);
    float* pb2s = (float*)(smem + O_PB2S);
    float* qacz = (float*)(smem + O_QACZ);
    float* mrgM = (float*)(smem + O_MRG_M);
    float* mrgS = (float*)(smem + O_MRG_S);
    float* mrgA = (float*)(smem + O_MRG_A);
    if (tid < 64) {
        pbps[tid] = g_pp[i * 64 + tid] + pb1g[tid];
        pb2s[tid] = pb2g[tid];
    }
    qacz[tid] = g_qa[i * HH + tid] + g_cz[tid];
    __syncthreads();

    const int lane = tid & 31, warp = tid >> 5;
    const int wb = warp * 16;
    const int rquad = lane >> 2;            // 0..7 row group
    const int tpair = lane & 3;             // 0..3
    const int l16 = lane & 15;
    const int r8 = l16 & 7, hf = l16 >> 3;
    const int pcol = 2 * tpair;
    const uint32_t lod = (lane >= 16) ? (uint32_t)LODELTA : 0u;
    const uint32_t base144 = sb + lod + (uint32_t)(r8 * 144 + hf * 16);
    const uint32_t base528 = sb + lod + O_W3 + (uint32_t)(r8 * 528 + hf * 16);

    // per-warp running softmax state for 16 owned columns (8 nt x 2 cols)
    float mS[16], sS[16], aS[16];
    #pragma unroll
    for (int t = 0; t < 16; ++t) { mS[t] = -1e30f; sS[t] = 0.f; aS[t] = 0.f; }

    for (int jt = 0; jt < 8; ++jt) {
        const int jr0 = jt * 128 + wb + rquad;

        // ===== h = relu(ppb_i - pp_j) frags (A of G1 and G2) =====
        uint32_t hH[4][4], hL[4][4];
        #pragma unroll
        for (int kt = 0; kt < 4; ++kt) {
            #pragma unroll
            for (int s2 = 0; s2 < 2; ++s2) {
                int kk = kt * 16 + s2 * 8 + pcol;
                float2 bb = *(const float2*)(pbps + kk);
                float2 p0 = *(const float2*)(g_pp + jr0 * 64 + kk);
                float2 p1 = *(const float2*)(g_pp + (jr0 + 8) * 64 + kk);
                split2(fmaxf(bb.x - p0.x, 0.f), fmaxf(bb.y - p0.y, 0.f),
                       hH[kt][s2 * 2 + 0], hL[kt][s2 * 2 + 0]);
                split2(fmaxf(bb.x - p1.x, 0.f), fmaxf(bb.y - p1.y, 0.f),
                       hH[kt][s2 * 2 + 1], hL[kt][s2 * 2 + 1]);
            }
        }

        // ===== G1: rpe = h @ W1 (K=64, N=64) =====
        float rp[8][4];
        #pragma unroll
        for (int nt = 0; nt < 8; ++nt) {
            #pragma unroll
            for (int r2 = 0; r2 < 4; ++r2) rp[nt][r2] = 0.f;
            #pragma unroll
            for (int kt = 0; kt < 4; ++kt)
                mma3(rp[nt], hH[kt], hL[kt], base144 + (uint32_t)(nt * 1152 + kt * 32));
        }

        // ===== G2 (z = h@M chunk) -> u -> G3 (sim += u@W3), H in 4 chunks =====
        float sa[8][4];
        #pragma unroll
        for (int nt = 0; nt < 8; ++nt)
            #pragma unroll
            for (int r2 = 0; r2 < 4; ++r2) sa[nt][r2] = 0.f;

        #pragma unroll
        for (int ci = 0; ci < 4; ++ci) {
            uint32_t uH[4][4], uL[4][4];
            #pragma unroll
            for (int nt = 0; nt < 8; ++nt) {
                float za[4] = {0.f, 0.f, 0.f, 0.f};
                #pragma unroll
                for (int kt = 0; kt < 4; ++kt)
                    mma3(za, hH[kt], hL[kt],
                         base144 + (uint32_t)(O_W2 + (ci * 64 + nt * 8) * 144 + kt * 32));
                int c = ci * 64 + 8 * nt + pcol;
                float2 qc = *(const float2*)(qacz + c);
                float2 k0 = *(const float2*)(g_ka + jr0 * HH + c);
                float2 k1 = *(const float2*)(g_ka + (jr0 + 8) * HH + c);
                int ktu = nt >> 1, rb = (nt & 1) * 2;
                split2(fmaxf(za[0] + qc.x - k0.x, 0.f), fmaxf(za[1] + qc.y - k0.y, 0.f),
                       uH[ktu][rb + 0], uL[ktu][rb + 0]);
                split2(fmaxf(za[2] + qc.x - k1.x, 0.f), fmaxf(za[3] + qc.y - k1.y, 0.f),
                       uH[ktu][rb + 1], uL[ktu][rb + 1]);
            }
            #pragma unroll
            for (int nt = 0; nt < 8; ++nt) {
                #pragma unroll
                for (int kt = 0; kt < 4; ++kt)
                    mma3(sa[nt], uH[kt], uL[kt],
                         base528 + (uint32_t)(nt * 4224 + ci * 128 + kt * 32));
            }
        }

        // ===== register-resident online softmax (per-warp stripe of 16 rows) =====
        #pragma unroll
        for (int nt = 0; nt < 8; ++nt) {
            int col = 8 * nt + pcol;
            float2 pbv = *(const float2*)(pb2s + col);
            float2 v0 = *(const float2*)(g_v + jr0 * 64 + col);
            float2 v1 = *(const float2*)(g_v + (jr0 + 8) * 64 + col);
            float vv00 = v0.x + rp[nt][0] + pbv.x, vv01 = v0.y + rp[nt][1] + pbv.y;
            float vv10 = v1.x + rp[nt][2] + pbv.x, vv11 = v1.y + rp[nt][3] + pbv.y;
            float lm0 = fmaxf(sa[nt][0], sa[nt][2]);
            float lm1 = fmaxf(sa[nt][1], sa[nt][3]);
            #pragma unroll
            for (int s = 4; s < 32; s <<= 1) {
                lm0 = fmaxf(lm0, __shfl_xor_sync(0xffffffffu, lm0, s));
                lm1 = fmaxf(lm1, __shfl_xor_sync(0xffffffffu, lm1, s));
            }
            float mn0 = fmaxf(mS[2 * nt + 0], lm0);
            float mn1 = fmaxf(mS[2 * nt + 1], lm1);
            float cr0 = __expf(mS[2 * nt + 0] - mn0);
            float cr1 = __expf(mS[2 * nt + 1] - mn1);
            float e00 = __expf(sa[nt][0] - mn0), e10 = __expf(sa[nt][2] - mn0);
            float e01 = __expf(sa[nt][1] - mn1), e11 = __expf(sa[nt][3] - mn1);
            float ps0 = e00 + e10, ps1 = e01 + e11;
            float pa0 = fmaf(e00, vv00, e10 * vv10);
            float pa1 = fmaf(e01, vv01, e11 * vv11);
            #pragma unroll
            for (int s = 4; s < 32; s <<= 1) {
                ps0 += __shfl_xor_sync(0xffffffffu, ps0, s);
                pa0 += __shfl_xor_sync(0xffffffffu, pa0, s);
                ps1 += __shfl_xor_sync(0xffffffffu, ps1, s);
                pa1 += __shfl_xor_sync(0xffffffffu, pa1, s);
            }
            sS[2 * nt + 0] = sS[2 * nt + 0] * cr0 + ps0;
            aS[2 * nt + 0] = aS[2 * nt + 0] * cr0 + pa0;
            mS[2 * nt + 0] = mn0;
            sS[2 * nt + 1] = sS[2 * nt + 1] * cr1 + ps1;
            aS[2 * nt + 1] = aS[2 * nt + 1] * cr1 + pa1;
            mS[2 * nt + 1] = mn1;
        }
    }

    // ===== cross-warp merge (8 stripe-partials per column) =====
    if (rquad == 0) {
        #pragma unroll
        for (int nt = 0; nt < 8; ++nt) {
            int c = 8 * nt + pcol;
            mrgM[warp * 64 + c] = mS[2 * nt + 0]; mrgM[warp * 64 + c + 1] = mS[2 * nt + 1];
            mrgS[warp * 64 + c] = sS[2 * nt + 0]; mrgS[warp * 64 + c + 1] = sS[2 * nt + 1];
            mrgA[warp * 64 + c] = aS[2 * nt + 0]; mrgA[warp * 64 + c + 1] = aS[2 * nt + 1];
        }
    }
    __syncthreads();
    if (tid < 64) {
        float M = -1e30f;
        #pragma unroll
        for (int w = 0; w < 8; ++w) M = fmaxf(M, mrgM[w * 64 + tid]);
        float S = 0.f, A = 0.f;
        #pragma unroll
        for (int w = 0; w < 8; ++w) {
            float e = __expf(mrgM[w * 64 + tid] - M);
            S = fmaf(mrgS[w * 64 + tid], e, S);
            A = fmaf(mrgA[w * 64 + tid], e, A);
        }
        out[i * 64 + tid] = A / S;
    }
}

// ---------------------------------------------------------------------------
extern "C" void kernel_launch(void* const* d_in, const int* in_sizes, int n_in,
                              void* d_out, int out_size)
{
    const float* x   = (const float*)d_in[0];
    const float* pos = (const float*)d_in[1];
    const float* Wq  = (const float*)d_in[2];
    const float* Wk  = (const float*)d_in[3];
    const float* Wv  = (const float*)d_in[4];
    const float* pW1 = (const float*)d_in[5];
    const float* pb1 = (const float*)d_in[6];
    const float* pW2 = (const float*)d_in[7];
    const float* pb2 = (const float*)d_in[8];
    const float* aW1 = (const float*)d_in[9];
    const float* ab1 = (const float*)d_in[10];
    const float* aW2 = (const float*)d_in[11];
    // d_in[12] = ab2: constant over j, cancels in per-channel softmax.
    float* out = (float*)d_out;
    (void)in_sizes; (void)n_in; (void)out_size;

    cudaFuncSetAttribute(pt_main, cudaFuncAttributeMaxDynamicSharedMemorySize, SMEM_TOTAL);

    dim3 pcB(64, 4);
    pt_precompute<<<NN / 4, pcB>>>(x, pos, Wq, Wk, Wv, pW1);
    pt_aux<<<NN + 64 + 1, 256>>>(aW1, pW2, pb2, ab1);
    wconvert<<<(DD*DD + HH*DD + DD*HH + 255) / 256, 256>>>(pW2, aW2);
    pt_main<<<NN, 256, SMEM_TOTAL>>>(pb1, pb2, out);
}

// round 6
// speedup vs baseline: 4.5749x; 1.0580x over previous
#include <cuda_runtime.h>
#include <cuda_bf16.h>
#include <stdint.h>
#include <math.h>

// PointTransformerLayer via bf16 HMMA (mma.sync m16n8k16), sm_103-safe PTX.
// B=1, N=1024, D=64, H_POS=64, H_ATTN=256.
// Algebra: pp = pos@pW1;  h = relu(pp_i - pp_j + pb1);  rpe = h@pW2
//   z = h@M + qa_i - ka_j + cz,  M = pW2@aW1, qa = q@aW1, ka = k@aW1, cz = pb2@aW1 + ab1
//   u = relu(z);  sim = u@aW2  (ab2 cancels in per-channel softmax)
//   out[i,d] = softmax_j(sim[:,d]) . (v[j,d] + rpe[j,d] + pb2[d])
// 3-term bf16 hi/lo split GEMMs (Ah*Bh + Ah*Bl + Al*Bh), fp32 accumulate.
// 32 j-rows per warp (2 m16 row-tiles share every ldmatrix B-fragment -> LDSM halved).
// Softmax state is 6 regs/thread (lane L owns cols 2L,2L+1; update when nt==rquad).
// vv (= v + rpe + pb2) lives in warp-private smem scratch; no main-loop barriers.

#define NN 1024
#define DD 64
#define HH 256

__device__ __align__(16) float g_q[NN*DD];
__device__ __align__(16) float g_k[NN*DD];
__device__ __align__(16) float g_v[NN*DD];
__device__ __align__(16) float g_pp[NN*DD];
__device__ __align__(16) float g_qa[NN*HH];
__device__ __align__(16) float g_ka[NN*HH];
__device__ __align__(16) float g_Mt[DD*HH];      // M[m][c] = sum_d pW2[m,d] aW1[d,c]
__device__ __align__(16) float g_cz[HH];
__device__ __align__(16) __nv_bfloat16 W1Hg[DD*DD],  W1Lg[DD*DD];   // pW2^T [d][m]
__device__ __align__(16) __nv_bfloat16 W2Hg[HH*DD],  W2Lg[HH*DD];   // M^T   [c][m]
__device__ __align__(16) __nv_bfloat16 W3Hg[DD*HH],  W3Lg[DD*HH];   // aW2^T [d][c]

// ---------------- smem layout (bytes) ----------------
// HI block: W1 @0 (64x144B), W2 @9216 (256x144B), W3 @46080 (64x528B) -> end 79872
// LO block mirrored at +LODELTA. vv scratch 256x64 f32. misc at end.
#define LODELTA 81920
#define O_W1 0
#define O_W2 9216
#define O_W3 46080
#define O_VV 161792
#define O_PBPS 227328
#define O_PB2S 227584
#define O_QACZ 227840
#define SMEM_TOTAL 228864

__device__ __forceinline__ uint32_t smem_u32(const void* p) {
    uint32_t a;
    asm("{ .reg .u64 t; cvta.to.shared.u64 t, %1; cvt.u32.u64 %0, t; }" : "=r"(a) : "l"(p));
    return a;
}
__device__ __forceinline__ void mma16816(float* c, const uint32_t* a, uint32_t b0, uint32_t b1) {
    asm volatile("mma.sync.aligned.m16n8k16.row.col.f32.bf16.bf16.f32 "
                 "{%0,%1,%2,%3}, {%4,%5,%6,%7}, {%8,%9}, {%0,%1,%2,%3};"
                 : "+f"(c[0]), "+f"(c[1]), "+f"(c[2]), "+f"(c[3])
                 : "r"(a[0]), "r"(a[1]), "r"(a[2]), "r"(a[3]), "r"(b0), "r"(b1));
}
// One x4 ldmatrix (hi b0,b1 + lo b0,b1 via +LODELTA mirror) feeds TWO row-tiles, 3 terms each.
__device__ __forceinline__ void mma3x2(float* c0, float* c1,
                                       const uint32_t* aH0, const uint32_t* aL0,
                                       const uint32_t* aH1, const uint32_t* aL1,
                                       uint32_t addr) {
    uint32_t h0, h1, l0, l1;
    asm volatile("ldmatrix.sync.aligned.m8n8.x4.shared.b16 {%0,%1,%2,%3}, [%4];"
                 : "=r"(h0), "=r"(h1), "=r"(l0), "=r"(l1) : "r"(addr));
    mma16816(c0, aH0, h0, h1);
    mma16816(c0, aH0, l0, l1);
    mma16816(c0, aL0, h0, h1);
    mma16816(c1, aH1, h0, h1);
    mma16816(c1, aH1, l0, l1);
    mma16816(c1, aL1, h0, h1);
}
__device__ __forceinline__ void split2(float a, float b, uint32_t& hi, uint32_t& lo) {
    __nv_bfloat162 hp = __floats2bfloat162_rn(a, b);
    uint32_t h = *reinterpret_cast<uint32_t*>(&hp);
    float af = __low2float(hp), bf = __high2float(hp);
    __nv_bfloat162 lp = __floats2bfloat162_rn(a - af, b - bf);
    hi = h;
    lo = *reinterpret_cast<uint32_t*>(&lp);
}

// ---------------- precompute: q,k,v,pp ----------------
__global__ void pt_precompute(const float* __restrict__ x, const float* __restrict__ pos,
                              const float* __restrict__ Wq, const float* __restrict__ Wk,
                              const float* __restrict__ Wv, const float* __restrict__ pW1)
{
    const int i = blockIdx.x * 4 + threadIdx.y;
    const int d = threadIdx.x;
    __shared__ float xr[4][DD];
    xr[threadIdx.y][d] = x[i * DD + d];
    __syncthreads();
    float aq = 0.f, ak = 0.f, av = 0.f;
    #pragma unroll 8
    for (int m = 0; m < DD; ++m) {
        float xv = xr[threadIdx.y][m];
        aq = fmaf(xv, Wq[m * DD + d], aq);
        ak = fmaf(xv, Wk[m * DD + d], ak);
        av = fmaf(xv, Wv[m * DD + d], av);
    }
    g_q[i * DD + d] = aq; g_k[i * DD + d] = ak; g_v[i * DD + d] = av;
    g_pp[i * DD + d] = pos[i * 2 + 0] * pW1[d] + pos[i * 2 + 1] * pW1[DD + d];
}

// ---------------- aux: qa, ka, M, cz ----------------
__global__ void pt_aux(const float* __restrict__ aW1, const float* __restrict__ pW2,
                       const float* __restrict__ pb2, const float* __restrict__ ab1)
{
    const int blk = blockIdx.x, c = threadIdx.x;
    __shared__ float sh[128];
    if (blk < NN) {
        if (c < 64) { sh[c] = g_q[blk * 64 + c]; sh[64 + c] = g_k[blk * 64 + c]; }
        __syncthreads();
        float accq = 0.f, acck = 0.f;
        #pragma unroll 8
        for (int dd = 0; dd < 64; ++dd) {
            float w = aW1[dd * HH + c];
            accq = fmaf(sh[dd], w, accq);
            acck = fmaf(sh[64 + dd], w, acck);
        }
        g_qa[blk * HH + c] = accq;
        g_ka[blk * HH + c] = acck;
    } else if (blk < NN + 64) {
        int m = blk - NN;
        if (c < 64) sh[c] = pW2[m * 64 + c];
        __syncthreads();
        float acc = 0.f;
        #pragma unroll 8
        for (int dd = 0; dd < 64; ++dd) acc = fmaf(sh[dd], aW1[dd * HH + c], acc);
        g_Mt[m * HH + c] = acc;
    } else {
        float acc = ab1[c];
        #pragma unroll 8
        for (int dd = 0; dd < 64; ++dd) acc = fmaf(pb2[dd], aW1[dd * HH + c], acc);
        g_cz[c] = acc;
    }
}

// ---------------- weight hi/lo split + transpose ----------------
__global__ void wconvert(const float* __restrict__ pW2, const float* __restrict__ aW2)
{
    int idx = blockIdx.x * blockDim.x + threadIdx.x;
    const int t1 = DD * DD, t2 = t1 + HH * DD, t3 = t2 + DD * HH;
    if (idx < t1) {
        int d = idx >> 6, m = idx & 63;
        float w = pW2[m * DD + d];
        __nv_bfloat16 h = __float2bfloat16(w);
        W1Hg[idx] = h; W1Lg[idx] = __float2bfloat16(w - __bfloat162float(h));
    } else if (idx < t2) {
        int k = idx - t1; int c = k >> 6, m = k & 63;
        float w = g_Mt[m * HH + c];
        __nv_bfloat16 h = __float2bfloat16(w);
        W2Hg[k] = h; W2Lg[k] = __float2bfloat16(w - __bfloat162float(h));
    } else if (idx < t3) {
        int k = idx - t2; int d = k >> 8, c = k & 255;
        float w = aW2[c * DD + d];
        __nv_bfloat16 h = __float2bfloat16(w);
        W3Hg[k] = h; W3Lg[k] = __float2bfloat16(w - __bfloat162float(h));
    }
}

// ---------------- main: one CTA per query i, 256 threads, j tiled by 256 ----------------
__global__ __launch_bounds__(256, 1) void pt_main(
    const float* __restrict__ pb1g, const float* __restrict__ pb2g,
    float* __restrict__ out)
{
    extern __shared__ __align__(16) char smem[];
    const uint32_t sb = smem_u32(smem);
    const int tid = threadIdx.x;
    const int i = blockIdx.x;

    // ---- stage weights: hi block + lo mirror at +LODELTA ----
    {
        const uint4* s;
        s = (const uint4*)W1Hg;
        for (int u = tid; u < 512; u += 256)
            *(uint4*)(smem + O_W1 + (u >> 3) * 144 + (u & 7) * 16) = s[u];
        s = (const uint4*)W1Lg;
        for (int u = tid; u < 512; u += 256)
            *(uint4*)(smem + O_W1 + LODELTA + (u >> 3) * 144 + (u & 7) * 16) = s[u];
        s = (const uint4*)W2Hg;
        for (int u = tid; u < 2048; u += 256)
            *(uint4*)(smem + O_W2 + (u >> 3) * 144 + (u & 7) * 16) = s[u];
        s = (const uint4*)W2Lg;
        for (int u = tid; u < 2048; u += 256)
            *(uint4*)(smem + O_W2 + LODELTA + (u >> 3) * 144 + (u & 7) * 16) = s[u];
        s = (const uint4*)W3Hg;
        for (int u = tid; u < 2048; u += 256)
            *(uint4*)(smem + O_W3 + (u >> 5) * 528 + (u & 31) * 16) = s[u];
        s = (const uint4*)W3Lg;
        for (int u = tid; u < 2048; u += 256)
            *(uint4*)(smem + O_W3 + LODELTA + (u >> 5) * 528 + (u & 31) * 16) = s[u];
    }
    float* pbps = (float*)(smem + O_PBPS);
    float* pb2s = (float*)(smem + O_PB2S);
    float* qacz = (float*)(smem + O_QACZ);
    float* vvb  = (float*)(smem + O_VV);
    if (tid < 64) {
        pbps[tid] = g_pp[i * 64 + tid] + pb1g[tid];
        pb2s[tid] = pb2g[tid];
    }
    qacz[tid] = g_qa[i * HH + tid] + g_cz[tid];
    __syncthreads();

    const int lane = tid & 31, warp = tid >> 5;
    const int wb32 = warp * 32;
    const int rquad = lane >> 2;            // 0..7
    const int tpair = lane & 3;             // 0..3
    const int l16 = lane & 15;
    const int r8 = l16 & 7, hf = l16 >> 3;
    const int pcol = 2 * tpair;
    const uint32_t lod = (lane >= 16) ? (uint32_t)LODELTA : 0u;
    const uint32_t base144 = sb + lod + (uint32_t)(r8 * 144 + hf * 16);
    const uint32_t base528 = sb + lod + O_W3 + (uint32_t)(r8 * 528 + hf * 16);

    // 6-reg softmax state: lane L owns columns 2L, 2L+1
    float mS0 = -1e30f, mS1 = -1e30f, sS0 = 0.f, sS1 = 0.f, aS0 = 0.f, aS1 = 0.f;

    #pragma unroll 1
    for (int jt = 0; jt < 4; ++jt) {
        const int j0 = jt * 256;

        // ===== h fragments for 2 row-tiles (A of G1 and G2) =====
        uint32_t hH[2][4][4], hL[2][4][4];
        #pragma unroll
        for (int rt = 0; rt < 2; ++rt) {
            const int jr = j0 + wb32 + rt * 16 + rquad;
            #pragma unroll
            for (int kt = 0; kt < 4; ++kt) {
                #pragma unroll
                for (int s2 = 0; s2 < 2; ++s2) {
                    int kk = kt * 16 + s2 * 8 + pcol;
                    float2 bb = *(const float2*)(pbps + kk);
                    float2 p0 = *(const float2*)(g_pp + jr * 64 + kk);
                    float2 p1 = *(const float2*)(g_pp + (jr + 8) * 64 + kk);
                    split2(fmaxf(bb.x - p0.x, 0.f), fmaxf(bb.y - p0.y, 0.f),
                           hH[rt][kt][s2 * 2 + 0], hL[rt][kt][s2 * 2 + 0]);
                    split2(fmaxf(bb.x - p1.x, 0.f), fmaxf(bb.y - p1.y, 0.f),
                           hH[rt][kt][s2 * 2 + 1], hL[rt][kt][s2 * 2 + 1]);
                }
            }
        }

        // ===== G1: rpe; vv = v + rpe + pb2 -> warp-private smem =====
        #pragma unroll
        for (int nt = 0; nt < 8; ++nt) {
            float rp0[4] = {0.f, 0.f, 0.f, 0.f};
            float rp1[4] = {0.f, 0.f, 0.f, 0.f};
            #pragma unroll
            for (int kt = 0; kt < 4; ++kt)
                mma3x2(rp0, rp1, hH[0][kt], hL[0][kt], hH[1][kt], hL[1][kt],
                       base144 + (uint32_t)(nt * 1152 + kt * 32));
            int col = 8 * nt + pcol;
            float2 pbv = *(const float2*)(pb2s + col);
            #pragma unroll
            for (int rt = 0; rt < 2; ++rt) {
                const float* rp = rt ? rp1 : rp0;
                #pragma unroll
                for (int h2 = 0; h2 < 2; ++h2) {
                    int rl = wb32 + rt * 16 + h2 * 8 + rquad;
                    float2 vg = *(const float2*)(g_v + (j0 + rl) * 64 + col);
                    int cs = col ^ ((rl & 7) << 3);
                    *(float2*)(vvb + rl * 64 + cs) =
                        make_float2(vg.x + rp[h2 * 2 + 0] + pbv.x,
                                    vg.y + rp[h2 * 2 + 1] + pbv.y);
                }
            }
        }

        // ===== G2 (z = h@M + qa - ka + cz -> u) fused into G3 (sim += u@W3) =====
        float sa0[8][4], sa1[8][4];
        #pragma unroll
        for (int nt = 0; nt < 8; ++nt)
            #pragma unroll
            for (int r2 = 0; r2 < 4; ++r2) { sa0[nt][r2] = 0.f; sa1[nt][r2] = 0.f; }

        #pragma unroll 1
        for (int ci = 0; ci < 4; ++ci) {
            uint32_t uH[2][4][4], uL[2][4][4];
            #pragma unroll
            for (int nt = 0; nt < 8; ++nt) {
                float za0[4] = {0.f, 0.f, 0.f, 0.f};
                float za1[4] = {0.f, 0.f, 0.f, 0.f};
                #pragma unroll
                for (int kt = 0; kt < 4; ++kt)
                    mma3x2(za0, za1, hH[0][kt], hL[0][kt], hH[1][kt], hL[1][kt],
                           base144 + (uint32_t)(O_W2 + (ci * 64 + nt * 8) * 144 + kt * 32));
                int c = ci * 64 + 8 * nt + pcol;
                float2 qc = *(const float2*)(qacz + c);
                int ktu = nt >> 1, rb = (nt & 1) * 2;
                #pragma unroll
                for (int rt = 0; rt < 2; ++rt) {
                    const float* za = rt ? za1 : za0;
                    int jr = j0 + wb32 + rt * 16 + rquad;
                    float2 k0 = *(const float2*)(g_ka + jr * HH + c);
                    float2 k1 = *(const float2*)(g_ka + (jr + 8) * HH + c);
                    split2(fmaxf(za[0] + qc.x - k0.x, 0.f), fmaxf(za[1] + qc.y - k0.y, 0.f),
                           uH[rt][ktu][rb + 0], uL[rt][ktu][rb + 0]);
                    split2(fmaxf(za[2] + qc.x - k1.x, 0.f), fmaxf(za[3] + qc.y - k1.y, 0.f),
                           uH[rt][ktu][rb + 1], uL[rt][ktu][rb + 1]);
                }
            }
            #pragma unroll
            for (int nt = 0; nt < 8; ++nt) {
                #pragma unroll
                for (int kt = 0; kt < 4; ++kt)
                    mma3x2(sa0[nt], sa1[nt], uH[0][kt], uL[0][kt], uH[1][kt], uL[1][kt],
                           base528 + (uint32_t)(nt * 4224 + ci * 128 + kt * 32));
            }
        }

        // ===== online softmax: butterfly over rquad; owner lanes (nt==rquad) keep state =====
        #pragma unroll
        for (int nt = 0; nt < 8; ++nt) {
            int col = 8 * nt + pcol;
            float lm0 = fmaxf(fmaxf(sa0[nt][0], sa0[nt][2]), fmaxf(sa1[nt][0], sa1[nt][2]));
            float lm1 = fmaxf(fmaxf(sa0[nt][1], sa0[nt][3]), fmaxf(sa1[nt][1], sa1[nt][3]));
            #pragma unroll
            for (int s = 4; s < 32; s <<= 1) {
                lm0 = fmaxf(lm0, __shfl_xor_sync(0xffffffffu, lm0, s));
                lm1 = fmaxf(lm1, __shfl_xor_sync(0xffffffffu, lm1, s));
            }
            float ps0 = 0.f, pa0 = 0.f, ps1 = 0.f, pa1 = 0.f;
            #pragma unroll
            for (int rt = 0; rt < 2; ++rt) {
                const float* sa = rt ? sa1[nt] : sa0[nt];
                #pragma unroll
                for (int h2 = 0; h2 < 2; ++h2) {
                    int rl = wb32 + rt * 16 + h2 * 8 + rquad;
                    int cs = col ^ ((rl & 7) << 3);
                    float2 vv2 = *(const float2*)(vvb + rl * 64 + cs);
                    float e0 = __expf(sa[h2 * 2 + 0] - lm0);
                    float e1 = __expf(sa[h2 * 2 + 1] - lm1);
                    ps0 += e0; pa0 = fmaf(e0, vv2.x, pa0);
                    ps1 += e1; pa1 = fmaf(e1, vv2.y, pa1);
                }
            }
            #pragma unroll
            for (int s = 4; s < 32; s <<= 1) {
                ps0 += __shfl_xor_sync(0xffffffffu, ps0, s);
                pa0 += __shfl_xor_sync(0xffffffffu, pa0, s);
                ps1 += __shfl_xor_sync(0xffffffffu, ps1, s);
                pa1 += __shfl_xor_sync(0xffffffffu, pa1, s);
            }
            if (rquad == nt) {
                float mn0 = fmaxf(mS0, lm0), mn1 = fmaxf(mS1, lm1);
                float c0 = __expf(mS0 - mn0), t0 = __expf(lm0 - mn0);
                float c1 = __expf(mS1 - mn1), t1 = __expf(lm1 - mn1);
                sS0 = sS0 * c0 + ps0 * t0;  aS0 = aS0 * c0 + pa0 * t0;  mS0 = mn0;
                sS1 = sS1 * c1 + ps1 * t1;  aS1 = aS1 * c1 + pa1 * t1;  mS1 = mn1;
            }
        }
    }

    // ===== cross-warp merge (overlay on dead vv scratch) =====
    __syncthreads();
    float* mrgM = (float*)(smem + O_VV);
    float* mrgS = (float*)(smem + O_VV + 2048);
    float* mrgA = (float*)(smem + O_VV + 4096);
    mrgM[warp * 64 + 2 * lane] = mS0;  mrgM[warp * 64 + 2 * lane + 1] = mS1;
    mrgS[warp * 64 + 2 * lane] = sS0;  mrgS[warp * 64 + 2 * lane + 1] = sS1;
    mrgA[warp * 64 + 2 * lane] = aS0;  mrgA[warp * 64 + 2 * lane + 1] = aS1;
    __syncthreads();
    if (tid < 64) {
        float M = -1e30f;
        #pragma unroll
        for (int w = 0; w < 8; ++w) M = fmaxf(M, mrgM[w * 64 + tid]);
        float S = 0.f, A = 0.f;
        #pragma unroll
        for (int w = 0; w < 8; ++w) {
            float e = __expf(mrgM[w * 64 + tid] - M);
            S = fmaf(mrgS[w * 64 + tid], e, S);
            A = fmaf(mrgA[w * 64 + tid], e, A);
        }
        out[i * 64 + tid] = A / S;
    }
}

// ---------------------------------------------------------------------------
extern "C" void kernel_launch(void* const* d_in, const int* in_sizes, int n_in,
                              void* d_out, int out_size)
{
    const float* x   = (const float*)d_in[0];
    const float* pos = (const float*)d_in[1];
    const float* Wq  = (const float*)d_in[2];
    const float* Wk  = (const float*)d_in[3];
    const float* Wv  = (const float*)d_in[4];
    const float* pW1 = (const float*)d_in[5];
    const float* pb1 = (const float*)d_in[6];
    const float* pW2 = (const float*)d_in[7];
    const float* pb2 = (const float*)d_in[8];
    const float* aW1 = (const float*)d_in[9];
    const float* ab1 = (const float*)d_in[10];
    const float* aW2 = (const float*)d_in[11];
    // d_in[12] = ab2: constant over j, cancels in per-channel softmax.
    float* out = (float*)d_out;
    (void)in_sizes; (void)n_in; (void)out_size;

    cudaFuncSetAttribute(pt_main, cudaFuncAttributeMaxDynamicSharedMemorySize, SMEM_TOTAL);

    dim3 pcB(64, 4);
    pt_precompute<<<NN / 4, pcB>>>(x, pos, Wq, Wk, Wv, pW1);
    pt_aux<<<NN + 64 + 1, 256>>>(aW1, pW2, pb2, ab1);
    wconvert<<<(DD*DD + HH*DD + DD*HH + 255) / 256, 256>>>(pW2, aW2);
    pt_main<<<NN, 256, SMEM_TOTAL>>>(pb1, pb2, out);
}

// round 7
// speedup vs baseline: 4.7221x; 1.0322x over previous
#include <cuda_runtime.h>
#include <cuda_bf16.h>
#include <stdint.h>
#include <math.h>

// PointTransformerLayer via bf16 HMMA (mma.sync m16n8k16), sm_103-safe PTX.
// B=1, N=1024, D=64, H_POS=64, H_ATTN=256.
// Algebra: pp = pos@pW1;  h = relu(pp_i - pp_j + pb1);  rpe = h@pW2
//   z = h@M + qa_i - ka_j + cz,  M = pW2@aW1, qa = q@aW1, ka = k@aW1, cz = pb2@aW1 + ab1
//   u = relu(z);  sim = u@aW2  (ab2 cancels in per-channel softmax)
//   out[i,d] = softmax_j(sim[:,d]) . (v[j,d] + rpe[j,d] + pb2[d])
// 3-term bf16 hi/lo split GEMMs (Ah*Bh + Ah*Bl + Al*Bh), fp32 accumulate.
// 32 j-rows per warp; G2->G3 interleaved at ktu granularity so the u-fragment
// working set is 16 regs (kills the R6 spills). 6-reg softmax state; no main-loop barriers.

#define NN 1024
#define DD 64
#define HH 256

__device__ __align__(16) float g_q[NN*DD];
__device__ __align__(16) float g_k[NN*DD];
__device__ __align__(16) float g_v[NN*DD];
__device__ __align__(16) float g_pp[NN*DD];
__device__ __align__(16) float g_qa[NN*HH];
__device__ __align__(16) float g_ka[NN*HH];
__device__ __align__(16) float g_Mt[DD*HH];      // M[m][c] = sum_d pW2[m,d] aW1[d,c]
__device__ __align__(16) float g_cz[HH];
__device__ __align__(16) __nv_bfloat16 W1Hg[DD*DD],  W1Lg[DD*DD];   // pW2^T [d][m]
__device__ __align__(16) __nv_bfloat16 W2Hg[HH*DD],  W2Lg[HH*DD];   // M^T   [c][m]
__device__ __align__(16) __nv_bfloat16 W3Hg[DD*HH],  W3Lg[DD*HH];   // aW2^T [d][c]

// ---------------- smem layout (bytes) ----------------
#define LODELTA 81920
#define O_W1 0
#define O_W2 9216
#define O_W3 46080
#define O_VV 161792
#define O_PBPS 227328
#define O_PB2S 227584
#define O_QACZ 227840
#define SMEM_TOTAL 228864

__device__ __forceinline__ uint32_t smem_u32(const void* p) {
    uint32_t a;
    asm("{ .reg .u64 t; cvta.to.shared.u64 t, %1; cvt.u32.u64 %0, t; }" : "=r"(a) : "l"(p));
    return a;
}
__device__ __forceinline__ void mma16816(float* c, const uint32_t* a, uint32_t b0, uint32_t b1) {
    asm volatile("mma.sync.aligned.m16n8k16.row.col.f32.bf16.bf16.f32 "
                 "{%0,%1,%2,%3}, {%4,%5,%6,%7}, {%8,%9}, {%0,%1,%2,%3};"
                 : "+f"(c[0]), "+f"(c[1]), "+f"(c[2]), "+f"(c[3])
                 : "r"(a[0]), "r"(a[1]), "r"(a[2]), "r"(a[3]), "r"(b0), "r"(b1));
}
// One x4 ldmatrix (hi b0,b1 + lo b0,b1 via +LODELTA lane-split mirror) feeds TWO row-tiles.
__device__ __forceinline__ void mma3x2(float* c0, float* c1,
                                       const uint32_t* aH0, const uint32_t* aL0,
                                       const uint32_t* aH1, const uint32_t* aL1,
                                       uint32_t addr) {
    uint32_t h0, h1, l0, l1;
    asm volatile("ldmatrix.sync.aligned.m8n8.x4.shared.b16 {%0,%1,%2,%3}, [%4];"
                 : "=r"(h0), "=r"(h1), "=r"(l0), "=r"(l1) : "r"(addr));
    mma16816(c0, aH0, h0, h1);
    mma16816(c0, aH0, l0, l1);
    mma16816(c0, aL0, h0, h1);
    mma16816(c1, aH1, h0, h1);
    mma16816(c1, aH1, l0, l1);
    mma16816(c1, aL1, h0, h1);
}
__device__ __forceinline__ void split2(float a, float b, uint32_t& hi, uint32_t& lo) {
    __nv_bfloat162 hp = __floats2bfloat162_rn(a, b);
    uint32_t h = *reinterpret_cast<uint32_t*>(&hp);
    float af = __low2float(hp), bf = __high2float(hp);
    __nv_bfloat162 lp = __floats2bfloat162_rn(a - af, b - bf);
    hi = h;
    lo = *reinterpret_cast<uint32_t*>(&lp);
}

// ---------------- precompute: q,k,v,pp ----------------
__global__ void pt_precompute(const float* __restrict__ x, const float* __restrict__ pos,
                              const float* __restrict__ Wq, const float* __restrict__ Wk,
                              const float* __restrict__ Wv, const float* __restrict__ pW1)
{
    const int i = blockIdx.x * 4 + threadIdx.y;
    const int d = threadIdx.x;
    __shared__ float xr[4][DD];
    xr[threadIdx.y][d] = x[i * DD + d];
    __syncthreads();
    float aq = 0.f, ak = 0.f, av = 0.f;
    #pragma unroll 8
    for (int m = 0; m < DD; ++m) {
        float xv = xr[threadIdx.y][m];
        aq = fmaf(xv, Wq[m * DD + d], aq);
        ak = fmaf(xv, Wk[m * DD + d], ak);
        av = fmaf(xv, Wv[m * DD + d], av);
    }
    g_q[i * DD + d] = aq; g_k[i * DD + d] = ak; g_v[i * DD + d] = av;
    g_pp[i * DD + d] = pos[i * 2 + 0] * pW1[d] + pos[i * 2 + 1] * pW1[DD + d];
}

// ---------------- aux: qa, ka, M, cz ----------------
__global__ void pt_aux(const float* __restrict__ aW1, const float* __restrict__ pW2,
                       const float* __restrict__ pb2, const float* __restrict__ ab1)
{
    const int blk = blockIdx.x, c = threadIdx.x;
    __shared__ float sh[128];
    if (blk < NN) {
        if (c < 64) { sh[c] = g_q[blk * 64 + c]; sh[64 + c] = g_k[blk * 64 + c]; }
        __syncthreads();
        float accq = 0.f, acck = 0.f;
        #pragma unroll 8
        for (int dd = 0; dd < 64; ++dd) {
            float w = aW1[dd * HH + c];
            accq = fmaf(sh[dd], w, accq);
            acck = fmaf(sh[64 + dd], w, acck);
        }
        g_qa[blk * HH + c] = accq;
        g_ka[blk * HH + c] = acck;
    } else if (blk < NN + 64) {
        int m = blk - NN;
        if (c < 64) sh[c] = pW2[m * 64 + c];
        __syncthreads();
        float acc = 0.f;
        #pragma unroll 8
        for (int dd = 0; dd < 64; ++dd) acc = fmaf(sh[dd], aW1[dd * HH + c], acc);
        g_Mt[m * HH + c] = acc;
    } else {
        float acc = ab1[c];
        #pragma unroll 8
        for (int dd = 0; dd < 64; ++dd) acc = fmaf(pb2[dd], aW1[dd * HH + c], acc);
        g_cz[c] = acc;
    }
}

// ---------------- weight hi/lo split + transpose ----------------
__global__ void wconvert(const float* __restrict__ pW2, const float* __restrict__ aW2)
{
    int idx = blockIdx.x * blockDim.x + threadIdx.x;
    const int t1 = DD * DD, t2 = t1 + HH * DD, t3 = t2 + DD * HH;
    if (idx < t1) {
        int d = idx >> 6, m = idx & 63;
        float w = pW2[m * DD + d];
        __nv_bfloat16 h = __float2bfloat16(w);
        W1Hg[idx] = h; W1Lg[idx] = __float2bfloat16(w - __bfloat162float(h));
    } else if (idx < t2) {
        int k = idx - t1; int c = k >> 6, m = k & 63;
        float w = g_Mt[m * HH + c];
        __nv_bfloat16 h = __float2bfloat16(w);
        W2Hg[k] = h; W2Lg[k] = __float2bfloat16(w - __bfloat162float(h));
    } else if (idx < t3) {
        int k = idx - t2; int d = k >> 8, c = k & 255;
        float w = aW2[c * DD + d];
        __nv_bfloat16 h = __float2bfloat16(w);
        W3Hg[k] = h; W3Lg[k] = __float2bfloat16(w - __bfloat162float(h));
    }
}

// ---------------- main: one CTA per query i, 256 threads, j tiled by 256 ----------------
__global__ __launch_bounds__(256, 1) void pt_main(
    const float* __restrict__ pb1g, const float* __restrict__ pb2g,
    float* __restrict__ out)
{
    extern __shared__ __align__(16) char smem[];
    const uint32_t sb = smem_u32(smem);
    const int tid = threadIdx.x;
    const int i = blockIdx.x;

    // ---- stage weights: hi block + lo mirror at +LODELTA ----
    {
        const uint4* s;
        s = (const uint4*)W1Hg;
        for (int u = tid; u < 512; u += 256)
            *(uint4*)(smem + O_W1 + (u >> 3) * 144 + (u & 7) * 16) = s[u];
        s = (const uint4*)W1Lg;
        for (int u = tid; u < 512; u += 256)
            *(uint4*)(smem + O_W1 + LODELTA + (u >> 3) * 144 + (u & 7) * 16) = s[u];
        s = (const uint4*)W2Hg;
        for (int u = tid; u < 2048; u += 256)
            *(uint4*)(smem + O_W2 + (u >> 3) * 144 + (u & 7) * 16) = s[u];
        s = (const uint4*)W2Lg;
        for (int u = tid; u < 2048; u += 256)
            *(uint4*)(smem + O_W2 + LODELTA + (u >> 3) * 144 + (u & 7) * 16) = s[u];
        s = (const uint4*)W3Hg;
        for (int u = tid; u < 2048; u += 256)
            *(uint4*)(smem + O_W3 + (u >> 5) * 528 + (u & 31) * 16) = s[u];
        s = (const uint4*)W3Lg;
        for (int u = tid; u < 2048; u += 256)
            *(uint4*)(smem + O_W3 + LODELTA + (u >> 5) * 528 + (u & 31) * 16) = s[u];
    }
    float* pbps = (float*)(smem + O_PBPS);
    float* pb2s = (float*)(smem + O_PB2S);
    float* qacz = (float*)(smem + O_QACZ);
    float* vvb  = (float*)(smem + O_VV);
    if (tid < 64) {
        pbps[tid] = g_pp[i * 64 + tid] + pb1g[tid];
        pb2s[tid] = pb2g[tid];
    }
    qacz[tid] = g_qa[i * HH + tid] + g_cz[tid];
    __syncthreads();

    const int lane = tid & 31, warp = tid >> 5;
    const int wb32 = warp * 32;
    const int rquad = lane >> 2;            // 0..7
    const int tpair = lane & 3;             // 0..3
    const int l16 = lane & 15;
    const int r8 = l16 & 7, hf = l16 >> 3;
    const int pcol = 2 * tpair;
    const uint32_t lod = (lane >= 16) ? (uint32_t)LODELTA : 0u;
    const uint32_t base144 = sb + lod + (uint32_t)(r8 * 144 + hf * 16);
    const uint32_t base528 = sb + lod + O_W3 + (uint32_t)(r8 * 528 + hf * 16);

    // 6-reg softmax state: lane L owns columns 2L, 2L+1
    float mS0 = -1e30f, mS1 = -1e30f, sS0 = 0.f, sS1 = 0.f, aS0 = 0.f, aS1 = 0.f;

    #pragma unroll 1
    for (int jt = 0; jt < 4; ++jt) {
        const int j0 = jt * 256;

        // ===== h fragments for 2 row-tiles (A of G1 and G2) =====
        uint32_t hH[2][4][4], hL[2][4][4];
        #pragma unroll
        for (int rt = 0; rt < 2; ++rt) {
            const int jr = j0 + wb32 + rt * 16 + rquad;
            #pragma unroll
            for (int kt = 0; kt < 4; ++kt) {
                #pragma unroll
                for (int s2 = 0; s2 < 2; ++s2) {
                    int kk = kt * 16 + s2 * 8 + pcol;
                    float2 bb = *(const float2*)(pbps + kk);
                    float2 p0 = *(const float2*)(g_pp + jr * 64 + kk);
                    float2 p1 = *(const float2*)(g_pp + (jr + 8) * 64 + kk);
                    split2(fmaxf(bb.x - p0.x, 0.f), fmaxf(bb.y - p0.y, 0.f),
                           hH[rt][kt][s2 * 2 + 0], hL[rt][kt][s2 * 2 + 0]);
                    split2(fmaxf(bb.x - p1.x, 0.f), fmaxf(bb.y - p1.y, 0.f),
                           hH[rt][kt][s2 * 2 + 1], hL[rt][kt][s2 * 2 + 1]);
                }
            }
        }

        // ===== G1: rpe; vv = v + rpe + pb2 -> warp-private smem =====
        #pragma unroll
        for (int nt = 0; nt < 8; ++nt) {
            float rp0[4] = {0.f, 0.f, 0.f, 0.f};
            float rp1[4] = {0.f, 0.f, 0.f, 0.f};
            #pragma unroll
            for (int kt = 0; kt < 4; ++kt)
                mma3x2(rp0, rp1, hH[0][kt], hL[0][kt], hH[1][kt], hL[1][kt],
                       base144 + (uint32_t)(nt * 1152 + kt * 32));
            int col = 8 * nt + pcol;
            float2 pbv = *(const float2*)(pb2s + col);
            #pragma unroll
            for (int rt = 0; rt < 2; ++rt) {
                const float* rp = rt ? rp1 : rp0;
                #pragma unroll
                for (int h2 = 0; h2 < 2; ++h2) {
                    int rl = wb32 + rt * 16 + h2 * 8 + rquad;
                    float2 vg = *(const float2*)(g_v + (j0 + rl) * 64 + col);
                    int cs = col ^ ((rl & 7) << 3);
                    *(float2*)(vvb + rl * 64 + cs) =
                        make_float2(vg.x + rp[h2 * 2 + 0] + pbv.x,
                                    vg.y + rp[h2 * 2 + 1] + pbv.y);
                }
            }
        }

        // ===== G2 -> u -> G3, interleaved per ktu (16 channels) to cap live registers =====
        float sa0[8][4], sa1[8][4];
        #pragma unroll
        for (int nt = 0; nt < 8; ++nt)
            #pragma unroll
            for (int r2 = 0; r2 < 4; ++r2) { sa0[nt][r2] = 0.f; sa1[nt][r2] = 0.f; }

        #pragma unroll 1
        for (int ci = 0; ci < 4; ++ci) {
            #pragma unroll 1
            for (int ktu = 0; ktu < 4; ++ktu) {
                uint32_t uH[2][4], uL[2][4];     // one k16 A-frag set per row-tile
                #pragma unroll
                for (int t = 0; t < 2; ++t) {
                    const int nt = 2 * ktu + t;
                    float za0[4] = {0.f, 0.f, 0.f, 0.f};
                    float za1[4] = {0.f, 0.f, 0.f, 0.f};
                    #pragma unroll
                    for (int kt = 0; kt < 4; ++kt)
                        mma3x2(za0, za1, hH[0][kt], hL[0][kt], hH[1][kt], hL[1][kt],
                               base144 + (uint32_t)(O_W2 + (ci * 64 + nt * 8) * 144 + kt * 32));
                    const int c = ci * 64 + 8 * nt + pcol;
                    float2 qc = *(const float2*)(qacz + c);
                    const int rb = t * 2;
                    #pragma unroll
                    for (int rt = 0; rt < 2; ++rt) {
                        const float* za = rt ? za1 : za0;
                        const int jr = j0 + wb32 + rt * 16 + rquad;
                        float2 k0 = *(const float2*)(g_ka + jr * HH + c);
                        float2 k1 = *(const float2*)(g_ka + (jr + 8) * HH + c);
                        split2(fmaxf(za[0] + qc.x - k0.x, 0.f), fmaxf(za[1] + qc.y - k0.y, 0.f),
                               uH[rt][rb + 0], uL[rt][rb + 0]);
                        split2(fmaxf(za[2] + qc.x - k1.x, 0.f), fmaxf(za[3] + qc.y - k1.y, 0.f),
                               uH[rt][rb + 1], uL[rt][rb + 1]);
                    }
                }
                #pragma unroll
                for (int nt = 0; nt < 8; ++nt)
                    mma3x2(sa0[nt], sa1[nt], uH[0], uL[0], uH[1], uL[1],
                           base528 + (uint32_t)(nt * 4224 + ci * 128 + ktu * 32));
            }
        }

        // ===== online softmax: butterfly over rquad; owner lanes (nt==rquad) keep state =====
        #pragma unroll
        for (int nt = 0; nt < 8; ++nt) {
            int col = 8 * nt + pcol;
            float lm0 = fmaxf(fmaxf(sa0[nt][0], sa0[nt][2]), fmaxf(sa1[nt][0], sa1[nt][2]));
            float lm1 = fmaxf(fmaxf(sa0[nt][1], sa0[nt][3]), fmaxf(sa1[nt][1], sa1[nt][3]));
            #pragma unroll
            for (int s = 4; s < 32; s <<= 1) {
                lm0 = fmaxf(lm0, __shfl_xor_sync(0xffffffffu, lm0, s));
                lm1 = fmaxf(lm1, __shfl_xor_sync(0xffffffffu, lm1, s));
            }
            float ps0 = 0.f, pa0 = 0.f, ps1 = 0.f, pa1 = 0.f;
            #pragma unroll
            for (int rt = 0; rt < 2; ++rt) {
                const float* sa = rt ? sa1[nt] : sa0[nt];
                #pragma unroll
                for (int h2 = 0; h2 < 2; ++h2) {
                    int rl = wb32 + rt * 16 + h2 * 8 + rquad;
                    int cs = col ^ ((rl & 7) << 3);
                    float2 vv2 = *(const float2*)(vvb + rl * 64 + cs);
                    float e0 = __expf(sa[h2 * 2 + 0] - lm0);
                    float e1 = __expf(sa[h2 * 2 + 1] - lm1);
                    ps0 += e0; pa0 = fmaf(e0, vv2.x, pa0);
                    ps1 += e1; pa1 = fmaf(e1, vv2.y, pa1);
                }
            }
            #pragma unroll
            for (int s = 4; s < 32; s <<= 1) {
                ps0 += __shfl_xor_sync(0xffffffffu, ps0, s);
                pa0 += __shfl_xor_sync(0xffffffffu, pa0, s);
                ps1 += __shfl_xor_sync(0xffffffffu, ps1, s);
                pa1 += __shfl_xor_sync(0xffffffffu, pa1, s);
            }
            if (rquad == nt) {
                float mn0 = fmaxf(mS0, lm0), mn1 = fmaxf(mS1, lm1);
                float c0 = __expf(mS0 - mn0), t0 = __expf(lm0 - mn0);
                float c1 = __expf(mS1 - mn1), t1 = __expf(lm1 - mn1);
                sS0 = sS0 * c0 + ps0 * t0;  aS0 = aS0 * c0 + pa0 * t0;  mS0 = mn0;
                sS1 = sS1 * c1 + ps1 * t1;  aS1 = aS1 * c1 + pa1 * t1;  mS1 = mn1;
            }
        }
    }

    // ===== cross-warp merge (overlay on dead vv scratch) =====
    __syncthreads();
    float* mrgM = (float*)(smem + O_VV);
    float* mrgS = (float*)(smem + O_VV + 2048);
    float* mrgA = (float*)(smem + O_VV + 4096);
    mrgM[warp * 64 + 2 * lane] = mS0;  mrgM[warp * 64 + 2 * lane + 1] = mS1;
    mrgS[warp * 64 + 2 * lane] = sS0;  mrgS[warp * 64 + 2 * lane + 1] = sS1;
    mrgA[warp * 64 + 2 * lane] = aS0;  mrgA[warp * 64 + 2 * lane + 1] = aS1;
    __syncthreads();
    if (tid < 64) {
        float M = -1e30f;
        #pragma unroll
        for (int w = 0; w < 8; ++w) M = fmaxf(M, mrgM[w * 64 + tid]);
        float S = 0.f, A = 0.f;
        #pragma unroll
        for (int w = 0; w < 8; ++w) {
            float e = __expf(mrgM[w * 64 + tid] - M);
            S = fmaf(mrgS[w * 64 + tid], e, S);
            A = fmaf(mrgA[w * 64 + tid], e, A);
        }
        out[i * 64 + tid] = A / S;
    }
}

// ---------------------------------------------------------------------------
extern "C" void kernel_launch(void* const* d_in, const int* in_sizes, int n_in,
                              void* d_out, int out_size)
{
    const float* x   = (const float*)d_in[0];
    const float* pos = (const float*)d_in[1];
    const float* Wq  = (const float*)d_in[2];
    const float* Wk  = (const float*)d_in[3];
    const float* Wv  = (const float*)d_in[4];
    const float* pW1 = (const float*)d_in[5];
    const float* pb1 = (const float*)d_in[6];
    const float* pW2 = (const float*)d_in[7];
    const float* pb2 = (const float*)d_in[8];
    const float* aW1 = (const float*)d_in[9];
    const float* ab1 = (const float*)d_in[10];
    const float* aW2 = (const float*)d_in[11];
    // d_in[12] = ab2: constant over j, cancels in per-channel softmax.
    float* out = (float*)d_out;
    (void)in_sizes; (void)n_in; (void)out_size;

    cudaFuncSetAttribute(pt_main, cudaFuncAttributeMaxDynamicSharedMemorySize, SMEM_TOTAL);

    dim3 pcB(64, 4);
    pt_precompute<<<NN / 4, pcB>>>(x, pos, Wq, Wk, Wv, pW1);
    pt_aux<<<NN + 64 + 1, 256>>>(aW1, pW2, pb2, ab1);
    wconvert<<<(DD*DD + HH*DD + DD*HH + 255) / 256, 256>>>(pW2, aW2);
    pt_main<<<NN, 256, SMEM_TOTAL>>>(pb1, pb2, out);
}

// round 10
// speedup vs baseline: 6.0883x; 1.2893x over previous
#include <cuda_runtime.h>
#include <cuda_bf16.h>
#include <stdint.h>
#include <math.h>

// PointTransformerLayer via bf16 HMMA (mma.sync m16n8k16), sm_103-safe PTX.
// B=1, N=1024, D=64, H_POS=64, H_ATTN=256.
// Algebra: pp = pos@pW1;  h = relu(pp_i - pp_j + pb1);  rpe = h@pW2
//   z = h@M + qa_i - ka_j + cz,  M = pW2@aW1, qa = q@aW1, ka = k@aW1, cz = pb2@aW1 + ab1
//   u = relu(z);  sim = u@aW2  (ab2 cancels in per-channel softmax)
//   out[i,d] = softmax_j(sim[:,d]) . (v[j,d] + rpe[j,d]) + pb2[d]   (pb2 deferred: sum(attn)=1)
// Splits: G1 3-term (AhBh+AhBl+AlBh, rpe is output-linear); G2/G3 2-term (AhBh+AhBl).
// W3 pre-scaled by log2(e): softmax uses raw exp2f. 32 j-rows/warp; ktu-interleaved
// G2->G3; 6-reg softmax state; no main-loop barriers.

#define NN 1024
#define DD 64
#define HH 256

__device__ __align__(16) float g_q[NN*DD];
__device__ __align__(16) float g_k[NN*DD];
__device__ __align__(16) float g_v[NN*DD];
__device__ __align__(16) float g_pp[NN*DD];
__device__ __align__(16) float g_qa[NN*HH];
__device__ __align__(16) float g_ka[NN*HH];
__device__ __align__(16) float g_Mt[DD*HH];      // M[m][c] = sum_d pW2[m,d] aW1[d,c]
__device__ __align__(16) float g_cz[HH];
__device__ __align__(16) __nv_bfloat16 W1Hg[DD*DD],  W1Lg[DD*DD];   // pW2^T [d][m]
__device__ __align__(16) __nv_bfloat16 W2Hg[HH*DD],  W2Lg[HH*DD];   // M^T   [c][m]
__device__ __align__(16) __nv_bfloat16 W3Hg[DD*HH],  W3Lg[DD*HH];   // (aW2*log2e)^T [d][c]

// ---------------- smem layout (bytes) ----------------
#define LODELTA 81920
#define O_W1 0
#define O_W2 9216
#define O_W3 46080
#define O_VV 161792
#define O_PBPS 227328
#define O_PB2S 227584
#define O_QACZ 227840
#define SMEM_TOTAL 228864

__device__ __forceinline__ uint32_t smem_u32(const void* p) {
    uint32_t a;
    asm("{ .reg .u64 t; cvta.to.shared.u64 t, %1; cvt.u32.u64 %0, t; }" : "=r"(a) : "l"(p));
    return a;
}
__device__ __forceinline__ void mma16816(float* c, const uint32_t* a, uint32_t b0, uint32_t b1) {
    asm volatile("mma.sync.aligned.m16n8k16.row.col.f32.bf16.bf16.f32 "
                 "{%0,%1,%2,%3}, {%4,%5,%6,%7}, {%8,%9}, {%0,%1,%2,%3};"
                 : "+f"(c[0]), "+f"(c[1]), "+f"(c[2]), "+f"(c[3])
                 : "r"(a[0]), "r"(a[1]), "r"(a[2]), "r"(a[3]), "r"(b0), "r"(b1));
}
// 3-term x2 row-tiles: one x4 ldmatrix (hi pair + lo pair via +LODELTA lane split).
__device__ __forceinline__ void mma3x2(float* c0, float* c1,
                                       const uint32_t* aH0, const uint32_t* aL0,
                                       const uint32_t* aH1, const uint32_t* aL1,
                                       uint32_t addr) {
    uint32_t h0, h1, l0, l1;
    asm volatile("ldmatrix.sync.aligned.m8n8.x4.shared.b16 {%0,%1,%2,%3}, [%4];"
                 : "=r"(h0), "=r"(h1), "=r"(l0), "=r"(l1) : "r"(addr));
    mma16816(c0, aH0, h0, h1);
    mma16816(c0, aH0, l0, l1);
    mma16816(c0, aL0, h0, h1);
    mma16816(c1, aH1, h0, h1);
    mma16816(c1, aH1, l0, l1);
    mma16816(c1, aL1, h0, h1);
}
// 2-term x2 row-tiles: A-hi only (AhBh + AhBl).
__device__ __forceinline__ void mma2x2(float* c0, float* c1,
                                       const uint32_t* aH0, const uint32_t* aH1,
                                       uint32_t addr) {
    uint32_t h0, h1, l0, l1;
    asm volatile("ldmatrix.sync.aligned.m8n8.x4.shared.b16 {%0,%1,%2,%3}, [%4];"
                 : "=r"(h0), "=r"(h1), "=r"(l0), "=r"(l1) : "r"(addr));
    mma16816(c0, aH0, h0, h1);
    mma16816(c0, aH0, l0, l1);
    mma16816(c1, aH1, h0, h1);
    mma16816(c1, aH1, l0, l1);
}
__device__ __forceinline__ void split2(float a, float b, uint32_t& hi, uint32_t& lo) {
    __nv_bfloat162 hp = __floats2bfloat162_rn(a, b);
    uint32_t h = *reinterpret_cast<uint32_t*>(&hp);
    float af = __low2float(hp), bf = __high2float(hp);
    __nv_bfloat162 lp = __floats2bfloat162_rn(a - af, b - bf);
    hi = h;
    lo = *reinterpret_cast<uint32_t*>(&lp);
}
__device__ __forceinline__ uint32_t pack2(float a, float b) {
    __nv_bfloat162 hp = __floats2bfloat162_rn(a, b);
    return *reinterpret_cast<uint32_t*>(&hp);
}

// ---------------- precompute: q,k,v,pp ----------------
__global__ void pt_precompute(const float* __restrict__ x, const float* __restrict__ pos,
                              const float* __restrict__ Wq, const float* __restrict__ Wk,
                              const float* __restrict__ Wv, const float* __restrict__ pW1)
{
    const int i = blockIdx.x * 4 + threadIdx.y;
    const int d = threadIdx.x;
    __shared__ float xr[4][DD];
    xr[threadIdx.y][d] = x[i * DD + d];
    __syncthreads();
    float aq = 0.f, ak = 0.f, av = 0.f;
    #pragma unroll 8
    for (int m = 0; m < DD; ++m) {
        float xv = xr[threadIdx.y][m];
        aq = fmaf(xv, Wq[m * DD + d], aq);
        ak = fmaf(xv, Wk[m * DD + d], ak);
        av = fmaf(xv, Wv[m * DD + d], av);
    }
    g_q[i * DD + d] = aq; g_k[i * DD + d] = ak; g_v[i * DD + d] = av;
    g_pp[i * DD + d] = pos[i * 2 + 0] * pW1[d] + pos[i * 2 + 1] * pW1[DD + d];
}

// ---------------- aux: qa, ka, M, cz ----------------
__global__ void pt_aux(const float* __restrict__ aW1, const float* __restrict__ pW2,
                       const float* __restrict__ pb2, const float* __restrict__ ab1)
{
    const int blk = blockIdx.x, c = threadIdx.x;
    __shared__ float sh[128];
    if (blk < NN) {
        if (c < 64) { sh[c] = g_q[blk * 64 + c]; sh[64 + c] = g_k[blk * 64 + c]; }
        __syncthreads();
        float accq = 0.f, acck = 0.f;
        #pragma unroll 8
        for (int dd = 0; dd < 64; ++dd) {
            float w = aW1[dd * HH + c];
            accq = fmaf(sh[dd], w, accq);
            acck = fmaf(sh[64 + dd], w, acck);
        }
        g_qa[blk * HH + c] = accq;
        g_ka[blk * HH + c] = acck;
    } else if (blk < NN + 64) {
        int m = blk - NN;
        if (c < 64) sh[c] = pW2[m * 64 + c];
        __syncthreads();
        float acc = 0.f;
        #pragma unroll 8
        for (int dd = 0; dd < 64; ++dd) acc = fmaf(sh[dd], aW1[dd * HH + c], acc);
        g_Mt[m * HH + c] = acc;
    } else {
        float acc = ab1[c];
        #pragma unroll 8
        for (int dd = 0; dd < 64; ++dd) acc = fmaf(pb2[dd], aW1[dd * HH + c], acc);
        g_cz[c] = acc;
    }
}

// ---------------- weight hi/lo split + transpose ----------------
__global__ void wconvert(const float* __restrict__ pW2, const float* __restrict__ aW2)
{
    const float LOG2E = 1.4426950408889634f;
    int idx = blockIdx.x * blockDim.x + threadIdx.x;
    const int t1 = DD * DD, t2 = t1 + HH * DD, t3 = t2 + DD * HH;
    if (idx < t1) {
        int d = idx >> 6, m = idx & 63;
        float w = pW2[m * DD + d];
        __nv_bfloat16 h = __float2bfloat16(w);
        W1Hg[idx] = h; W1Lg[idx] = __float2bfloat16(w - __bfloat162float(h));
    } else if (idx < t2) {
        int k = idx - t1; int c = k >> 6, m = k & 63;
        float w = g_Mt[m * HH + c];
        __nv_bfloat16 h = __float2bfloat16(w);
        W2Hg[k] = h; W2Lg[k] = __float2bfloat16(w - __bfloat162float(h));
    } else if (idx < t3) {
        int k = idx - t2; int d = k >> 8, c = k & 255;
        float w = aW2[c * DD + d] * LOG2E;          // fold log2(e): softmax uses exp2
        __nv_bfloat16 h = __float2bfloat16(w);
        W3Hg[k] = h; W3Lg[k] = __float2bfloat16(w - __bfloat162float(h));
    }
}

// ---------------- main: one CTA per query i, 256 threads, j tiled by 256 ----------------
__global__ __launch_bounds__(256, 1) void pt_main(
    const float* __restrict__ pb1g, const float* __restrict__ pb2g,
    float* __restrict__ out)
{
    extern __shared__ __align__(16) char smem[];
    const uint32_t sb = smem_u32(smem);
    const int tid = threadIdx.x;
    const int i = blockIdx.x;

    // ---- stage weights: hi block + lo mirror at +LODELTA ----
    {
        const uint4* s;
        s = (const uint4*)W1Hg;
        for (int u = tid; u < 512; u += 256)
            *(uint4*)(smem + O_W1 + (u >> 3) * 144 + (u & 7) * 16) = s[u];
        s = (const uint4*)W1Lg;
        for (int u = tid; u < 512; u += 256)
            *(uint4*)(smem + O_W1 + LODELTA + (u >> 3) * 144 + (u & 7) * 16) = s[u];
        s = (const uint4*)W2Hg;
        for (int u = tid; u < 2048; u += 256)
            *(uint4*)(smem + O_W2 + (u >> 3) * 144 + (u & 7) * 16) = s[u];
        s = (const uint4*)W2Lg;
        for (int u = tid; u < 2048; u += 256)
            *(uint4*)(smem + O_W2 + LODELTA + (u >> 3) * 144 + (u & 7) * 16) = s[u];
        s = (const uint4*)W3Hg;
        for (int u = tid; u < 2048; u += 256)
            *(uint4*)(smem + O_W3 + (u >> 5) * 528 + (u & 31) * 16) = s[u];
        s = (const uint4*)W3Lg;
        for (int u = tid; u < 2048; u += 256)
            *(uint4*)(smem + O_W3 + LODELTA + (u >> 5) * 528 + (u & 31) * 16) = s[u];
    }
    float* pbps = (float*)(smem + O_PBPS);
    float* pb2s = (float*)(smem + O_PB2S);
    float* qacz = (float*)(smem + O_QACZ);
    float* vvb  = (float*)(smem + O_VV);
    if (tid < 64) {
        pbps[tid] = g_pp[i * 64 + tid] + pb1g[tid];
        pb2s[tid] = pb2g[tid];
    }
    qacz[tid] = g_qa[i * HH + tid] + g_cz[tid];
    __syncthreads();

    const int lane = tid & 31, warp = tid >> 5;
    const int wb32 = warp * 32;
    const int rquad = lane >> 2;            // 0..7
    const int tpair = lane & 3;             // 0..3
    const int l16 = lane & 15;
    const int r8 = l16 & 7, hf = l16 >> 3;
    const int pcol = 2 * tpair;
    const uint32_t lod = (lane >= 16) ? (uint32_t)LODELTA : 0u;
    const uint32_t base144 = sb + lod + (uint32_t)(r8 * 144 + hf * 16);
    const uint32_t base528 = sb + lod + O_W3 + (uint32_t)(r8 * 528 + hf * 16);

    // 6-reg softmax state: lane L owns columns 2L, 2L+1 (scaled = log2 domain)
    float mS0 = -1e30f, mS1 = -1e30f, sS0 = 0.f, sS1 = 0.f, aS0 = 0.f, aS1 = 0.f;

    #pragma unroll 1
    for (int jt = 0; jt < 4; ++jt) {
        const int j0 = jt * 256;

        // ===== h fragments for 2 row-tiles (A of G1 3-term, G2 2-term) =====
        uint32_t hH[2][4][4], hL[2][4][4];
        #pragma unroll
        for (int rt = 0; rt < 2; ++rt) {
            const int jr = j0 + wb32 + rt * 16 + rquad;
            #pragma unroll
            for (int kt = 0; kt < 4; ++kt) {
                #pragma unroll
                for (int s2 = 0; s2 < 2; ++s2) {
                    int kk = kt * 16 + s2 * 8 + pcol;
                    float2 bb = *(const float2*)(pbps + kk);
                    float2 p0 = *(const float2*)(g_pp + jr * 64 + kk);
                    float2 p1 = *(const float2*)(g_pp + (jr + 8) * 64 + kk);
                    split2(fmaxf(bb.x - p0.x, 0.f), fmaxf(bb.y - p0.y, 0.f),
                           hH[rt][kt][s2 * 2 + 0], hL[rt][kt][s2 * 2 + 0]);
                    split2(fmaxf(bb.x - p1.x, 0.f), fmaxf(bb.y - p1.y, 0.f),
                           hH[rt][kt][s2 * 2 + 1], hL[rt][kt][s2 * 2 + 1]);
                }
            }
        }

        // ===== G1 (3-term): rpe; vv = v + rpe -> warp-private smem (pb2 deferred) =====
        #pragma unroll
        for (int nt = 0; nt < 8; ++nt) {
            float rp0[4] = {0.f, 0.f, 0.f, 0.f};
            float rp1[4] = {0.f, 0.f, 0.f, 0.f};
            #pragma unroll
            for (int kt = 0; kt < 4; ++kt)
                mma3x2(rp0, rp1, hH[0][kt], hL[0][kt], hH[1][kt], hL[1][kt],
                       base144 + (uint32_t)(nt * 1152 + kt * 32));
            int col = 8 * nt + pcol;
            #pragma unroll
            for (int rt = 0; rt < 2; ++rt) {
                const float* rp = rt ? rp1 : rp0;
                #pragma unroll
                for (int h2 = 0; h2 < 2; ++h2) {
                    int rl = wb32 + rt * 16 + h2 * 8 + rquad;
                    float2 vg = *(const float2*)(g_v + (j0 + rl) * 64 + col);
                    int cs = col ^ ((rl & 7) << 3);
                    *(float2*)(vvb + rl * 64 + cs) =
                        make_float2(vg.x + rp[h2 * 2 + 0], vg.y + rp[h2 * 2 + 1]);
                }
            }
        }

        // ===== G2 (2-term) -> u -> G3 (2-term), interleaved per ktu =====
        float sa0[8][4], sa1[8][4];
        #pragma unroll
        for (int nt = 0; nt < 8; ++nt)
            #pragma unroll
            for (int r2 = 0; r2 < 4; ++r2) { sa0[nt][r2] = 0.f; sa1[nt][r2] = 0.f; }

        #pragma unroll 1
        for (int ci = 0; ci < 4; ++ci) {
            #pragma unroll 1
            for (int ktu = 0; ktu < 4; ++ktu) {
                uint32_t uH[2][4];               // A-hi frags only (2-term G3)
                #pragma unroll
                for (int t = 0; t < 2; ++t) {
                    const int nt = 2 * ktu + t;
                    float za0[4] = {0.f, 0.f, 0.f, 0.f};
                    float za1[4] = {0.f, 0.f, 0.f, 0.f};
                    #pragma unroll
                    for (int kt = 0; kt < 4; ++kt)
                        mma2x2(za0, za1, hH[0][kt], hH[1][kt],
                               base144 + (uint32_t)(O_W2 + (ci * 64 + nt * 8) * 144 + kt * 32));
                    const int c = ci * 64 + 8 * nt + pcol;
                    float2 qc = *(const float2*)(qacz + c);
                    const int rb = t * 2;
                    #pragma unroll
                    for (int rt = 0; rt < 2; ++rt) {
                        const float* za = rt ? za1 : za0;
                        const int jr = j0 + wb32 + rt * 16 + rquad;
                        float2 k0 = *(const float2*)(g_ka + jr * HH + c);
                        float2 k1 = *(const float2*)(g_ka + (jr + 8) * HH + c);
                        uH[rt][rb + 0] = pack2(fmaxf(za[0] + qc.x - k0.x, 0.f),
                                               fmaxf(za[1] + qc.y - k0.y, 0.f));
                        uH[rt][rb + 1] = pack2(fmaxf(za[2] + qc.x - k1.x, 0.f),
                                               fmaxf(za[3] + qc.y - k1.y, 0.f));
                    }
                }
                #pragma unroll
                for (int nt = 0; nt < 8; ++nt)
                    mma2x2(sa0[nt], sa1[nt], uH[0], uH[1],
                           base528 + (uint32_t)(nt * 4224 + ci * 128 + ktu * 32));
            }
        }

        // ===== online softmax (log2 domain): butterfly over rquad; owner nt==rquad =====
        #pragma unroll
        for (int nt = 0; nt < 8; ++nt) {
            int col = 8 * nt + pcol;
            float lm0 = fmaxf(fmaxf(sa0[nt][0], sa0[nt][2]), fmaxf(sa1[nt][0], sa1[nt][2]));
            float lm1 = fmaxf(fmaxf(sa0[nt][1], sa0[nt][3]), fmaxf(sa1[nt][1], sa1[nt][3]));
            #pragma unroll
            for (int s = 4; s < 32; s <<= 1) {
                lm0 = fmaxf(lm0, __shfl_xor_sync(0xffffffffu, lm0, s));
                lm1 = fmaxf(lm1, __shfl_xor_sync(0xffffffffu, lm1, s));
            }
            float ps0 = 0.f, pa0 = 0.f, ps1 = 0.f, pa1 = 0.f;
            #pragma unroll
            for (int rt = 0; rt < 2; ++rt) {
                const float* sa = rt ? sa1[nt] : sa0[nt];
                #pragma unroll
                for (int h2 = 0; h2 < 2; ++h2) {
                    int rl = wb32 + rt * 16 + h2 * 8 + rquad;
                    int cs = col ^ ((rl & 7) << 3);
                    float2 vv2 = *(const float2*)(vvb + rl * 64 + cs);
                    float e0 = exp2f(sa[h2 * 2 + 0] - lm0);
                    float e1 = exp2f(sa[h2 * 2 + 1] - lm1);
                    ps0 += e0; pa0 = fmaf(e0, vv2.x, pa0);
                    ps1 += e1; pa1 = fmaf(e1, vv2.y, pa1);
                }
            }
            #pragma unroll
            for (int s = 4; s < 32; s <<= 1) {
                ps0 += __shfl_xor_sync(0xffffffffu, ps0, s);
                pa0 += __shfl_xor_sync(0xffffffffu, pa0, s);
                ps1 += __shfl_xor_sync(0xffffffffu, ps1, s);
                pa1 += __shfl_xor_sync(0xffffffffu, pa1, s);
            }
            if (rquad == nt) {
                float mn0 = fmaxf(mS0, lm0), mn1 = fmaxf(mS1, lm1);
                float c0 = exp2f(mS0 - mn0), t0 = exp2f(lm0 - mn0);
                float c1 = exp2f(mS1 - mn1), t1 = exp2f(lm1 - mn1);
                sS0 = sS0 * c0 + ps0 * t0;  aS0 = aS0 * c0 + pa0 * t0;  mS0 = mn0;
                sS1 = sS1 * c1 + ps1 * t1;  aS1 = aS1 * c1 + pa1 * t1;  mS1 = mn1;
            }
        }
    }

    // ===== cross-warp merge (overlay on dead vv scratch); add deferred pb2 =====
    __syncthreads();
    float* mrgM = (float*)(smem + O_VV);
    float* mrgS = (float*)(smem + O_VV + 2048);
    float* mrgA = (float*)(smem + O_VV + 4096);
    mrgM[warp * 64 + 2 * lane] = mS0;  mrgM[warp * 64 + 2 * lane + 1] = mS1;
    mrgS[warp * 64 + 2 * lane] = sS0;  mrgS[warp * 64 + 2 * lane + 1] = sS1;
    mrgA[warp * 64 + 2 * lane] = aS0;  mrgA[warp * 64 + 2 * lane + 1] = aS1;
    __syncthreads();
    if (tid < 64) {
        float M = -1e30f;
        #pragma unroll
        for (int w = 0; w < 8; ++w) M = fmaxf(M, mrgM[w * 64 + tid]);
        float S = 0.f, A = 0.f;
        #pragma unroll
        for (int w = 0; w < 8; ++w) {
            float e = exp2f(mrgM[w * 64 + tid] - M);
            S = fmaf(mrgS[w * 64 + tid], e, S);
            A = fmaf(mrgA[w * 64 + tid], e, A);
        }
        out[i * 64 + tid] = A / S + pb2s[tid];
    }
}

// ---------------------------------------------------------------------------
extern "C" void kernel_launch(void* const* d_in, const int* in_sizes, int n_in,
                              void* d_out, int out_size)
{
    const float* x   = (const float*)d_in[0];
    const float* pos = (const float*)d_in[1];
    const float* Wq  = (const float*)d_in[2];
    const float* Wk  = (const float*)d_in[3];
    const float* Wv  = (const float*)d_in[4];
    const float* pW1 = (const float*)d_in[5];
    const float* pb1 = (const float*)d_in[6];
    const float* pW2 = (const float*)d_in[7];
    const float* pb2 = (const float*)d_in[8];
    const float* aW1 = (const float*)d_in[9];
    const float* ab1 = (const float*)d_in[10];
    const float* aW2 = (const float*)d_in[11];
    // d_in[12] = ab2: constant over j, cancels in per-channel softmax.
    float* out = (float*)d_out;
    (void)in_sizes; (void)n_in; (void)out_size;

    cudaFuncSetAttribute(pt_main, cudaFuncAttributeMaxDynamicSharedMemorySize, SMEM_TOTAL);

    dim3 pcB(64, 4);
    pt_precompute<<<NN / 4, pcB>>>(x, pos, Wq, Wk, Wv, pW1);
    pt_aux<<<NN + 64 + 1, 256>>>(aW1, pW2, pb2, ab1);
    wconvert<<<(DD*DD + HH*DD + DD*HH + 255) / 256, 256>>>(pW2, aW2);
    pt_main<<<NN, 256, SMEM_TOTAL>>>(pb1, pb2, out);
}

// round 11
// speedup vs baseline: 7.9065x; 1.2986x over previous
#include <cuda_runtime.h>
#include <cuda_bf16.h>
#include <stdint.h>
#include <math.h>

// PointTransformerLayer via bf16 HMMA (mma.sync m16n8k16), sm_103-safe PTX.
// B=1, N=1024, D=64, H_POS=64, H_ATTN=256.
// Algebra: pp = pos@pW1;  h = relu(pp_i - pp_j + pb1);  rpe = h@pW2
//   z = h@M + qa_i - ka_j + cz,  M = pW2@aW1, qa = q@aW1, ka = k@aW1, cz = pb2@aW1 + ab1
//   u = relu(z);  sim = u@aW2  (ab2 cancels in per-channel softmax)
//   out[i,d] = softmax_j(sim[:,d]) . (v[j,d] + rpe[j,d]) + pb2[d]   (pb2 deferred: sum(attn)=1)
// Splits: G1 3-term (rpe is output-linear); G2/G3 1-term pure bf16 with PAIRED-K ldmatrix
// (lanes 16-31 fetch the next k16 chunk instead of a lo mirror: 1 LDSM -> 4 MMAs).
// W3 pre-scaled by log2(e): softmax in exp2. 32 j-rows/warp; 6-reg softmax state;
// no main-loop barriers. smem 152KB (W2/W3 lo mirrors eliminated).

#define NN 1024
#define DD 64
#define HH 256

__device__ __align__(16) float g_q[NN*DD];
__device__ __align__(16) float g_k[NN*DD];
__device__ __align__(16) float g_v[NN*DD];
__device__ __align__(16) float g_pp[NN*DD];
__device__ __align__(16) float g_qa[NN*HH];
__device__ __align__(16) float g_ka[NN*HH];
__device__ __align__(16) float g_Mt[DD*HH];      // M[m][c] = sum_d pW2[m,d] aW1[d,c]
__device__ __align__(16) float g_cz[HH];
__device__ __align__(16) __nv_bfloat16 W1Hg[DD*DD], W1Lg[DD*DD];   // pW2^T [d][m]
__device__ __align__(16) __nv_bfloat16 W2Hg[HH*DD];                // M^T   [c][m]
__device__ __align__(16) __nv_bfloat16 W3Hg[DD*HH];                // (aW2*log2e)^T [d][c]

// ---------------- smem layout (bytes) ----------------
// W1 hi @0 (64x144B) | W2 hi @9216 (256x144B) | W3 hi @46080 (64x528B) -> 79872
// W1 lo @79872 (LODELTA mirror for G1's 3-term lane split) -> 89088
// vv @89088 (256x64 f32, 64KB) -> 154624 | misc -> 156160
#define LODELTA 79872
#define O_W1 0
#define O_W2 9216
#define O_W3 46080
#define O_VV 89088
#define O_PBPS 154624
#define O_PB2S 154880
#define O_QACZ 155136
#define SMEM_TOTAL 156160

__device__ __forceinline__ uint32_t smem_u32(const void* p) {
    uint32_t a;
    asm("{ .reg .u64 t; cvta.to.shared.u64 t, %1; cvt.u32.u64 %0, t; }" : "=r"(a) : "l"(p));
    return a;
}
__device__ __forceinline__ void mma16816(float* c, const uint32_t* a, uint32_t b0, uint32_t b1) {
    asm volatile("mma.sync.aligned.m16n8k16.row.col.f32.bf16.bf16.f32 "
                 "{%0,%1,%2,%3}, {%4,%5,%6,%7}, {%8,%9}, {%0,%1,%2,%3};"
                 : "+f"(c[0]), "+f"(c[1]), "+f"(c[2]), "+f"(c[3])
                 : "r"(a[0]), "r"(a[1]), "r"(a[2]), "r"(a[3]), "r"(b0), "r"(b1));
}
// 3-term x2 row-tiles: x4 ldmatrix = hi pair (lanes<16) + lo pair (lanes>=16, +LODELTA).
__device__ __forceinline__ void mma3x2(float* c0, float* c1,
                                       const uint32_t* aH0, const uint32_t* aL0,
                                       const uint32_t* aH1, const uint32_t* aL1,
                                       uint32_t addr) {
    uint32_t h0, h1, l0, l1;
    asm volatile("ldmatrix.sync.aligned.m8n8.x4.shared.b16 {%0,%1,%2,%3}, [%4];"
                 : "=r"(h0), "=r"(h1), "=r"(l0), "=r"(l1) : "r"(addr));
    mma16816(c0, aH0, h0, h1);
    mma16816(c0, aH0, l0, l1);
    mma16816(c0, aL0, h0, h1);
    mma16816(c1, aH1, h0, h1);
    mma16816(c1, aH1, l0, l1);
    mma16816(c1, aL1, h0, h1);
}
// 1-term paired-k: x4 ldmatrix = chunk kA b-pair (lanes<16) + chunk kB b-pair (lanes>=16, +32B).
// a*kA / a*kB are the A-frags for the two k16 chunks; 2 row-tiles -> 4 MMAs per LDSM.
__device__ __forceinline__ void mma1x2k2(float* c0, float* c1,
                                         const uint32_t* a0kA, const uint32_t* a0kB,
                                         const uint32_t* a1kA, const uint32_t* a1kB,
                                         uint32_t addr) {
    uint32_t m0, m1, m2, m3;
    asm volatile("ldmatrix.sync.aligned.m8n8.x4.shared.b16 {%0,%1,%2,%3}, [%4];"
                 : "=r"(m0), "=r"(m1), "=r"(m2), "=r"(m3) : "r"(addr));
    mma16816(c0, a0kA, m0, m1);
    mma16816(c1, a1kA, m0, m1);
    mma16816(c0, a0kB, m2, m3);
    mma16816(c1, a1kB, m2, m3);
}
__device__ __forceinline__ void split2(float a, float b, uint32_t& hi, uint32_t& lo) {
    __nv_bfloat162 hp = __floats2bfloat162_rn(a, b);
    uint32_t h = *reinterpret_cast<uint32_t*>(&hp);
    float af = __low2float(hp), bf = __high2float(hp);
    __nv_bfloat162 lp = __floats2bfloat162_rn(a - af, b - bf);
    hi = h;
    lo = *reinterpret_cast<uint32_t*>(&lp);
}
__device__ __forceinline__ uint32_t pack2(float a, float b) {
    __nv_bfloat162 hp = __floats2bfloat162_rn(a, b);
    return *reinterpret_cast<uint32_t*>(&hp);
}

// ---------------- precompute: q,k,v,pp ----------------
__global__ void pt_precompute(const float* __restrict__ x, const float* __restrict__ pos,
                              const float* __restrict__ Wq, const float* __restrict__ Wk,
                              const float* __restrict__ Wv, const float* __restrict__ pW1)
{
    const int i = blockIdx.x * 4 + threadIdx.y;
    const int d = threadIdx.x;
    __shared__ float xr[4][DD];
    xr[threadIdx.y][d] = x[i * DD + d];
    __syncthreads();
    float aq = 0.f, ak = 0.f, av = 0.f;
    #pragma unroll 8
    for (int m = 0; m < DD; ++m) {
        float xv = xr[threadIdx.y][m];
        aq = fmaf(xv, Wq[m * DD + d], aq);
        ak = fmaf(xv, Wk[m * DD + d], ak);
        av = fmaf(xv, Wv[m * DD + d], av);
    }
    g_q[i * DD + d] = aq; g_k[i * DD + d] = ak; g_v[i * DD + d] = av;
    g_pp[i * DD + d] = pos[i * 2 + 0] * pW1[d] + pos[i * 2 + 1] * pW1[DD + d];
}

// ---------------- aux: qa, ka, M, cz ----------------
__global__ void pt_aux(const float* __restrict__ aW1, const float* __restrict__ pW2,
                       const float* __restrict__ pb2, const float* __restrict__ ab1)
{
    const int blk = blockIdx.x, c = threadIdx.x;
    __shared__ float sh[128];
    if (blk < NN) {
        if (c < 64) { sh[c] = g_q[blk * 64 + c]; sh[64 + c] = g_k[blk * 64 + c]; }
        __syncthreads();
        float accq = 0.f, acck = 0.f;
        #pragma unroll 8
        for (int dd = 0; dd < 64; ++dd) {
            float w = aW1[dd * HH + c];
            accq = fmaf(sh[dd], w, accq);
            acck = fmaf(sh[64 + dd], w, acck);
        }
        g_qa[blk * HH + c] = accq;
        g_ka[blk * HH + c] = acck;
    } else if (blk < NN + 64) {
        int m = blk - NN;
        if (c < 64) sh[c] = pW2[m * 64 + c];
        __syncthreads();
        float acc = 0.f;
        #pragma unroll 8
        for (int dd = 0; dd < 64; ++dd) acc = fmaf(sh[dd], aW1[dd * HH + c], acc);
        g_Mt[m * HH + c] = acc;
    } else {
        float acc = ab1[c];
        #pragma unroll 8
        for (int dd = 0; dd < 64; ++dd) acc = fmaf(pb2[dd], aW1[dd * HH + c], acc);
        g_cz[c] = acc;
    }
}

// ---------------- weight convert ----------------
__global__ void wconvert(const float* __restrict__ pW2, const float* __restrict__ aW2)
{
    const float LOG2E = 1.4426950408889634f;
    int idx = blockIdx.x * blockDim.x + threadIdx.x;
    const int t1 = DD * DD, t2 = t1 + HH * DD, t3 = t2 + DD * HH;
    if (idx < t1) {
        int d = idx >> 6, m = idx & 63;
        float w = pW2[m * DD + d];
        __nv_bfloat16 h = __float2bfloat16(w);
        W1Hg[idx] = h; W1Lg[idx] = __float2bfloat16(w - __bfloat162float(h));
    } else if (idx < t2) {
        int k = idx - t1; int c = k >> 6, m = k & 63;
        W2Hg[k] = __float2bfloat16(g_Mt[m * HH + c]);
    } else if (idx < t3) {
        int k = idx - t2; int d = k >> 8, c = k & 255;
        W3Hg[k] = __float2bfloat16(aW2[c * DD + d] * LOG2E);
    }
}

// ---------------- main: one CTA per query i, 256 threads, j tiled by 256 ----------------
__global__ __launch_bounds__(256, 1) void pt_main(
    const float* __restrict__ pb1g, const float* __restrict__ pb2g,
    float* __restrict__ out)
{
    extern __shared__ __align__(16) char smem[];
    const uint32_t sb = smem_u32(smem);
    const int tid = threadIdx.x;
    const int i = blockIdx.x;

    // ---- stage weights ----
    {
        const uint4* s;
        s = (const uint4*)W1Hg;
        for (int u = tid; u < 512; u += 256)
            *(uint4*)(smem + O_W1 + (u >> 3) * 144 + (u & 7) * 16) = s[u];
        s = (const uint4*)W1Lg;
        for (int u = tid; u < 512; u += 256)
            *(uint4*)(smem + O_W1 + LODELTA + (u >> 3) * 144 + (u & 7) * 16) = s[u];
        s = (const uint4*)W2Hg;
        for (int u = tid; u < 2048; u += 256)
            *(uint4*)(smem + O_W2 + (u >> 3) * 144 + (u & 7) * 16) = s[u];
        s = (const uint4*)W3Hg;
        for (int u = tid; u < 2048; u += 256)
            *(uint4*)(smem + O_W3 + (u >> 5) * 528 + (u & 31) * 16) = s[u];
    }
    float* pbps = (float*)(smem + O_PBPS);
    float* pb2s = (float*)(smem + O_PB2S);
    float* qacz = (float*)(smem + O_QACZ);
    float* vvb  = (float*)(smem + O_VV);
    if (tid < 64) {
        pbps[tid] = g_pp[i * 64 + tid] + pb1g[tid];
        pb2s[tid] = pb2g[tid];
    }
    qacz[tid] = g_qa[i * HH + tid] + g_cz[tid];
    __syncthreads();

    const int lane = tid & 31, warp = tid >> 5;
    const int wb32 = warp * 32;
    const int rquad = lane >> 3 << 1 | ((lane >> 2) & 1);  // == lane>>2, written to match below
    const int tpair = lane & 3;
    const int l16 = lane & 15;
    const int r8 = l16 & 7, hf = l16 >> 3;
    const int pcol = 2 * tpair;
    const uint32_t lodW1 = (lane >= 16) ? (uint32_t)LODELTA : 0u;   // G1 lo mirror
    const uint32_t klod  = (lane >= 16) ? 32u : 0u;                 // G2/G3 next-k chunk
    const uint32_t base144_3 = sb + lodW1 + (uint32_t)(r8 * 144 + hf * 16);
    const uint32_t base144_1 = sb + klod + (uint32_t)(O_W2 + r8 * 144 + hf * 16);
    const uint32_t base528_1 = sb + klod + (uint32_t)(O_W3 + r8 * 528 + hf * 16);

    // 6-reg softmax state: lane L owns columns 2L, 2L+1 (log2 domain)
    float mS0 = -1e30f, mS1 = -1e30f, sS0 = 0.f, sS1 = 0.f, aS0 = 0.f, aS1 = 0.f;

    #pragma unroll 1
    for (int jt = 0; jt < 4; ++jt) {
        const int j0 = jt * 256;

        // ===== h fragments for 2 row-tiles =====
        uint32_t hH[2][4][4], hL[2][4][4];
        #pragma unroll
        for (int rt = 0; rt < 2; ++rt) {
            const int jr = j0 + wb32 + rt * 16 + (lane >> 2);
            #pragma unroll
            for (int kt = 0; kt < 4; ++kt) {
                #pragma unroll
                for (int s2 = 0; s2 < 2; ++s2) {
                    int kk = kt * 16 + s2 * 8 + pcol;
                    float2 bb = *(const float2*)(pbps + kk);
                    float2 p0 = *(const float2*)(g_pp + jr * 64 + kk);
                    float2 p1 = *(const float2*)(g_pp + (jr + 8) * 64 + kk);
                    split2(fmaxf(bb.x - p0.x, 0.f), fmaxf(bb.y - p0.y, 0.f),
                           hH[rt][kt][s2 * 2 + 0], hL[rt][kt][s2 * 2 + 0]);
                    split2(fmaxf(bb.x - p1.x, 0.f), fmaxf(bb.y - p1.y, 0.f),
                           hH[rt][kt][s2 * 2 + 1], hL[rt][kt][s2 * 2 + 1]);
                }
            }
        }

        // ===== G1 (3-term): rpe; vv = v + rpe -> warp-private smem =====
        #pragma unroll
        for (int nt = 0; nt < 8; ++nt) {
            float rp0[4] = {0.f, 0.f, 0.f, 0.f};
            float rp1[4] = {0.f, 0.f, 0.f, 0.f};
            #pragma unroll
            for (int kt = 0; kt < 4; ++kt)
                mma3x2(rp0, rp1, hH[0][kt], hL[0][kt], hH[1][kt], hL[1][kt],
                       base144_3 + (uint32_t)(nt * 1152 + kt * 32));
            int col = 8 * nt + pcol;
            #pragma unroll
            for (int rt = 0; rt < 2; ++rt) {
                const float* rp = rt ? rp1 : rp0;
                #pragma unroll
                for (int h2 = 0; h2 < 2; ++h2) {
                    int rl = wb32 + rt * 16 + h2 * 8 + (lane >> 2);
                    float2 vg = *(const float2*)(g_v + (j0 + rl) * 64 + col);
                    int cs = col ^ ((rl & 7) << 3);
                    *(float2*)(vvb + rl * 64 + cs) =
                        make_float2(vg.x + rp[h2 * 2 + 0], vg.y + rp[h2 * 2 + 1]);
                }
            }
        }

        // ===== G2 (1-term paired-k) -> u -> G3 (1-term paired-k), per k32 pair =====
        float sa0[8][4], sa1[8][4];
        #pragma unroll
        for (int nt = 0; nt < 8; ++nt)
            #pragma unroll
            for (int r2 = 0; r2 < 4; ++r2) { sa0[nt][r2] = 0.f; sa1[nt][r2] = 0.f; }

        #pragma unroll 1
        for (int ci = 0; ci < 4; ++ci) {
            #pragma unroll 1
            for (int kp = 0; kp < 2; ++kp) {     // pair of k16 u-chunks = 32 channels
                uint32_t uH[2][8];               // [row-tile][chunk*4 + frag]
                #pragma unroll
                for (int tt = 0; tt < 4; ++tt) {
                    const int nt = 4 * kp + tt;
                    float za0[4] = {0.f, 0.f, 0.f, 0.f};
                    float za1[4] = {0.f, 0.f, 0.f, 0.f};
                    #pragma unroll
                    for (int kt2 = 0; kt2 < 2; ++kt2)
                        mma1x2k2(za0, za1,
                                 hH[0][2 * kt2], hH[0][2 * kt2 + 1],
                                 hH[1][2 * kt2], hH[1][2 * kt2 + 1],
                                 base144_1 + (uint32_t)((ci * 64 + nt * 8) * 144 + kt2 * 64));
                    const int c = ci * 64 + 8 * nt + pcol;
                    float2 qc = *(const float2*)(qacz + c);
                    const int fb = (tt >> 1) * 4 + (tt & 1) * 2;
                    #pragma unroll
                    for (int rt = 0; rt < 2; ++rt) {
                        const float* za = rt ? za1 : za0;
                        const int jr = j0 + wb32 + rt * 16 + (lane >> 2);
                        float2 k0 = *(const float2*)(g_ka + jr * HH + c);
                        float2 k1 = *(const float2*)(g_ka + (jr + 8) * HH + c);
                        uH[rt][fb + 0] = pack2(fmaxf(za[0] + qc.x - k0.x, 0.f),
                                               fmaxf(za[1] + qc.y - k0.y, 0.f));
                        uH[rt][fb + 1] = pack2(fmaxf(za[2] + qc.x - k1.x, 0.f),
                                               fmaxf(za[3] + qc.y - k1.y, 0.f));
                    }
                }
                #pragma unroll
                for (int nt2 = 0; nt2 < 8; ++nt2)
                    mma1x2k2(sa0[nt2], sa1[nt2], uH[0] + 0, uH[0] + 4, uH[1] + 0, uH[1] + 4,
                             base528_1 + (uint32_t)(nt2 * 4224 + ci * 128 + kp * 64));
            }
        }

        // ===== online softmax (log2 domain): butterfly over rquad; owner nt==lane>>2 =====
        #pragma unroll
        for (int nt = 0; nt < 8; ++nt) {
            int col = 8 * nt + pcol;
            float lm0 = fmaxf(fmaxf(sa0[nt][0], sa0[nt][2]), fmaxf(sa1[nt][0], sa1[nt][2]));
            float lm1 = fmaxf(fmaxf(sa0[nt][1], sa0[nt][3]), fmaxf(sa1[nt][1], sa1[nt][3]));
            #pragma unroll
            for (int s = 4; s < 32; s <<= 1) {
                lm0 = fmaxf(lm0, __shfl_xor_sync(0xffffffffu, lm0, s));
                lm1 = fmaxf(lm1, __shfl_xor_sync(0xffffffffu, lm1, s));
            }
            float ps0 = 0.f, pa0 = 0.f, ps1 = 0.f, pa1 = 0.f;
            #pragma unroll
            for (int rt = 0; rt < 2; ++rt) {
                const float* sa = rt ? sa1[nt] : sa0[nt];
                #pragma unroll
                for (int h2 = 0; h2 < 2; ++h2) {
                    int rl = wb32 + rt * 16 + h2 * 8 + (lane >> 2);
                    int cs = col ^ ((rl & 7) << 3);
                    float2 vv2 = *(const float2*)(vvb + rl * 64 + cs);
                    float e0 = exp2f(sa[h2 * 2 + 0] - lm0);
                    float e1 = exp2f(sa[h2 * 2 + 1] - lm1);
                    ps0 += e0; pa0 = fmaf(e0, vv2.x, pa0);
                    ps1 += e1; pa1 = fmaf(e1, vv2.y, pa1);
                }
            }
            #pragma unroll
            for (int s = 4; s < 32; s <<= 1) {
                ps0 += __shfl_xor_sync(0xffffffffu, ps0, s);
                pa0 += __shfl_xor_sync(0xffffffffu, pa0, s);
                ps1 += __shfl_xor_sync(0xffffffffu, ps1, s);
                pa1 += __shfl_xor_sync(0xffffffffu, pa1, s);
            }
            if ((lane >> 2) == nt) {
                float mn0 = fmaxf(mS0, lm0), mn1 = fmaxf(mS1, lm1);
                float c0 = exp2f(mS0 - mn0), t0 = exp2f(lm0 - mn0);
                float c1 = exp2f(mS1 - mn1), t1 = exp2f(lm1 - mn1);
                sS0 = sS0 * c0 + ps0 * t0;  aS0 = aS0 * c0 + pa0 * t0;  mS0 = mn0;
                sS1 = sS1 * c1 + ps1 * t1;  aS1 = aS1 * c1 + pa1 * t1;  mS1 = mn1;
            }
        }
    }

    // ===== cross-warp merge (overlay on dead vv scratch); add deferred pb2 =====
    __syncthreads();
    float* mrgM = (float*)(smem + O_VV);
    float* mrgS = (float*)(smem + O_VV + 2048);
    float* mrgA = (float*)(smem + O_VV + 4096);
    mrgM[warp * 64 + 2 * lane] = mS0;  mrgM[warp * 64 + 2 * lane + 1] = mS1;
    mrgS[warp * 64 + 2 * lane] = sS0;  mrgS[warp * 64 + 2 * lane + 1] = sS1;
    mrgA[warp * 64 + 2 * lane] = aS0;  mrgA[warp * 64 + 2 * lane + 1] = aS1;
    __syncthreads();
    if (tid < 64) {
        float M = -1e30f;
        #pragma unroll
        for (int w = 0; w < 8; ++w) M = fmaxf(M, mrgM[w * 64 + tid]);
        float S = 0.f, A = 0.f;
        #pragma unroll
        for (int w = 0; w < 8; ++w) {
            float e = exp2f(mrgM[w * 64 + tid] - M);
            S = fmaf(mrgS[w * 64 + tid], e, S);
            A = fmaf(mrgA[w * 64 + tid], e, A);
        }
        out[i * 64 + tid] = A / S + pb2s[tid];
    }
}

// ---------------------------------------------------------------------------
extern "C" void kernel_launch(void* const* d_in, const int* in_sizes, int n_in,
                              void* d_out, int out_size)
{
    const float* x   = (const float*)d_in[0];
    const float* pos = (const float*)d_in[1];
    const float* Wq  = (const float*)d_in[2];
    const float* Wk  = (const float*)d_in[3];
    const float* Wv  = (const float*)d_in[4];
    const float* pW1 = (const float*)d_in[5];
    const float* pb1 = (const float*)d_in[6];
    const float* pW2 = (const float*)d_in[7];
    const float* pb2 = (const float*)d_in[8];
    const float* aW1 = (const float*)d_in[9];
    const float* ab1 = (const float*)d_in[10];
    const float* aW2 = (const float*)d_in[11];
    // d_in[12] = ab2: constant over j, cancels in per-channel softmax.
    float* out = (float*)d_out;
    (void)in_sizes; (void)n_in; (void)out_size;

    cudaFuncSetAttribute(pt_main, cudaFuncAttributeMaxDynamicSharedMemorySize, SMEM_TOTAL);

    dim3 pcB(64, 4);
    pt_precompute<<<NN / 4, pcB>>>(x, pos, Wq, Wk, Wv, pW1);
    pt_aux<<<NN + 64 + 1, 256>>>(aW1, pW2, pb2, ab1);
    wconvert<<<(DD*DD + HH*DD + DD*HH + 255) / 256, 256>>>(pW2, aW2);
    pt_main<<<NN, 256, SMEM_TOTAL>>>(pb1, pb2, out);
}